// round 1
// baseline (speedup 1.0000x reference)
#include <cuda_runtime.h>
#include <cuda_bf16.h>
#include <math.h>

// Problem constants (fixed shapes)
#define B_    2
#define S_    2048
#define H_    16
#define D_    64
#define HID   1024
#define QKV_  1024          // H_*D_
#define M_TOK 4096          // B_*S_
#define N_QKV 3072          // 3*QKV_
#define SCALE 0.125f        // 64^-0.5

// Scratch (device globals — no allocation allowed)
__device__ float g_qkv[(size_t)M_TOK * N_QKV];   // [token][3*QKV]
__device__ float g_att[(size_t)M_TOK * QKV_];    // [token][QKV] (B,S,H,D merged)

// ---------------------------------------------------------------------------
// NT GEMM: C[M][N] = A[M][K] * B[N][K]^T + bias[N]
// 64x64 tile, 256 threads (16x16), 4x4 microtile, BK=32
// ---------------------------------------------------------------------------
#define BM 64
#define BN 64
#define BK 32
#define LDT 68   // smem row stride (floats): 68*4=272 bytes, 16B aligned, low conflicts

__global__ __launch_bounds__(256) void gemm_nt_bias(
    const float* __restrict__ A,
    const float* __restrict__ B,
    const float* __restrict__ bias,
    float* __restrict__ C,
    int M, int N, int K)
{
    __shared__ float As[BK * LDT];   // As[k][m]
    __shared__ float Bs[BK * LDT];   // Bs[k][n]

    const int tid = threadIdx.x;
    const int tx  = tid & 15;
    const int ty  = tid >> 4;
    const int bm  = blockIdx.y * BM;
    const int bn  = blockIdx.x * BN;

    // loader mapping: row = tid/8 (+32), k = (tid%8)*4
    const int lr = tid >> 3;        // 0..31
    const int lk = (tid & 7) << 2;  // 0,4,...,28

    float acc[4][4];
#pragma unroll
    for (int i = 0; i < 4; i++)
#pragma unroll
        for (int j = 0; j < 4; j++) acc[i][j] = 0.f;

    for (int k0 = 0; k0 < K; k0 += BK) {
#pragma unroll
        for (int p = 0; p < 2; p++) {
            int r = lr + p * 32;
            float4 va = *(const float4*)&A[(size_t)(bm + r) * K + k0 + lk];
            As[(lk + 0) * LDT + r] = va.x;
            As[(lk + 1) * LDT + r] = va.y;
            As[(lk + 2) * LDT + r] = va.z;
            As[(lk + 3) * LDT + r] = va.w;
            float4 vb = *(const float4*)&B[(size_t)(bn + r) * K + k0 + lk];
            Bs[(lk + 0) * LDT + r] = vb.x;
            Bs[(lk + 1) * LDT + r] = vb.y;
            Bs[(lk + 2) * LDT + r] = vb.z;
            Bs[(lk + 3) * LDT + r] = vb.w;
        }
        __syncthreads();

#pragma unroll 8
        for (int k = 0; k < BK; k++) {
            float4 a = *(const float4*)&As[k * LDT + ty * 4];
            float4 b = *(const float4*)&Bs[k * LDT + tx * 4];
            float av[4] = {a.x, a.y, a.z, a.w};
            float bv[4] = {b.x, b.y, b.z, b.w};
#pragma unroll
            for (int i = 0; i < 4; i++)
#pragma unroll
                for (int j = 0; j < 4; j++)
                    acc[i][j] = fmaf(av[i], bv[j], acc[i][j]);
        }
        __syncthreads();
    }

    float4 bs4 = *(const float4*)&bias[bn + tx * 4];
    float bb[4] = {bs4.x, bs4.y, bs4.z, bs4.w};
#pragma unroll
    for (int i = 0; i < 4; i++) {
        float4 r;
        r.x = acc[i][0] + bb[0];
        r.y = acc[i][1] + bb[1];
        r.z = acc[i][2] + bb[2];
        r.w = acc[i][3] + bb[3];
        *(float4*)&C[(size_t)(bm + ty * 4 + i) * N + bn + tx * 4] = r;
    }
}

// ---------------------------------------------------------------------------
// Flash attention (fp32). One block = one (b,h) x one 64-row q tile.
// 256 threads (16x16), each owns a 4x4 microtile of the 64x64 score/output.
// Dynamic smem: Qs[d][m] (64x68), KPs (K^T then reused as P^T, 64x68),
// Vs[n][dd] (64x68)  => 52224 bytes.
// ---------------------------------------------------------------------------
#define ATT_SMEM (3 * 64 * LDT * 4)

__global__ __launch_bounds__(256) void attn_kernel(
    const float* __restrict__ qkv,  // [M_TOK][3*QKV]
    float* __restrict__ out)        // [M_TOK][QKV]
{
    extern __shared__ float sm[];
    float* Qs  = sm;                 // Qs[d*LDT + m]
    float* KPs = sm + 64 * LDT;      // Ks[d*LDT + n]  -> later Ps[n*LDT + m]
    float* Vs  = sm + 2 * 64 * LDT;  // Vs[n*LDT + dd]

    const int tid = threadIdx.x;
    const int tx  = tid & 15;
    const int ty  = tid >> 4;
    const int qt  = blockIdx.x;       // q tile 0..31
    const int bh  = blockIdx.y;       // 0..31
    const int b   = bh >> 4;
    const int h   = bh & 15;
    const int q0  = qt * 64;
    const size_t tok_base = (size_t)b * S_;
    const int hcol = h * D_;

    // load Q tile (transposed into Qs[d][m])
    {
        const int lm = tid >> 4;        // 0..15
        const int ld = (tid & 15) << 2; // 0..60
#pragma unroll
        for (int p = 0; p < 4; p++) {
            int m = lm + p * 16;
            size_t tok = tok_base + q0 + m;
            float4 v = *(const float4*)&qkv[tok * N_QKV + hcol + ld];
            Qs[(ld + 0) * LDT + m] = v.x;
            Qs[(ld + 1) * LDT + m] = v.y;
            Qs[(ld + 2) * LDT + m] = v.z;
            Qs[(ld + 3) * LDT + m] = v.w;
        }
    }

    float acc[4][4];
    float mrow[4], lrow[4];
#pragma unroll
    for (int i = 0; i < 4; i++) {
        mrow[i] = -INFINITY;
        lrow[i] = 0.f;
#pragma unroll
        for (int j = 0; j < 4; j++) acc[i][j] = 0.f;
    }
    __syncthreads();

    for (int kt = 0; kt < S_ / 64; kt++) {
        const int n0 = kt * 64;
        // load K (transposed) and V (direct)
        {
            const int ln = tid >> 4;
            const int ld = (tid & 15) << 2;
#pragma unroll
            for (int p = 0; p < 4; p++) {
                int n = ln + p * 16;
                size_t tok = tok_base + n0 + n;
                const float* rowp = &qkv[tok * N_QKV];
                float4 kv = *(const float4*)&rowp[QKV_ + hcol + ld];
                KPs[(ld + 0) * LDT + n] = kv.x;
                KPs[(ld + 1) * LDT + n] = kv.y;
                KPs[(ld + 2) * LDT + n] = kv.z;
                KPs[(ld + 3) * LDT + n] = kv.w;
                float4 vv = *(const float4*)&rowp[2 * QKV_ + hcol + ld];
                *(float4*)&Vs[n * LDT + ld] = vv;
            }
        }
        __syncthreads();

        // scores: s[i][j] = sum_d Q[m][d]*K[n][d],  m=ty*4+i, n=tx*4+j
        float s[4][4];
#pragma unroll
        for (int i = 0; i < 4; i++)
#pragma unroll
            for (int j = 0; j < 4; j++) s[i][j] = 0.f;

#pragma unroll 8
        for (int d = 0; d < 64; d++) {
            float4 a = *(const float4*)&Qs[d * LDT + ty * 4];
            float4 bq = *(const float4*)&KPs[d * LDT + tx * 4];
            float av[4] = {a.x, a.y, a.z, a.w};
            float bv[4] = {bq.x, bq.y, bq.z, bq.w};
#pragma unroll
            for (int i = 0; i < 4; i++)
#pragma unroll
                for (int j = 0; j < 4; j++)
                    s[i][j] = fmaf(av[i], bv[j], s[i][j]);
        }

        // online softmax update (per-row stats replicated across 16 tx lanes)
        float p[4][4];
#pragma unroll
        for (int i = 0; i < 4; i++) {
            float rmax = -INFINITY;
#pragma unroll
            for (int j = 0; j < 4; j++) {
                s[i][j] *= SCALE;
                rmax = fmaxf(rmax, s[i][j]);
            }
#pragma unroll
            for (int off = 8; off > 0; off >>= 1)
                rmax = fmaxf(rmax, __shfl_xor_sync(0xffffffffu, rmax, off));
            float mnew = fmaxf(mrow[i], rmax);
            float corr = __expf(mrow[i] - mnew);
            float rsum = 0.f;
#pragma unroll
            for (int j = 0; j < 4; j++) {
                p[i][j] = __expf(s[i][j] - mnew);
                rsum += p[i][j];
            }
#pragma unroll
            for (int off = 8; off > 0; off >>= 1)
                rsum += __shfl_xor_sync(0xffffffffu, rsum, off);
            lrow[i] = lrow[i] * corr + rsum;
            mrow[i] = mnew;
#pragma unroll
            for (int j = 0; j < 4; j++) acc[i][j] *= corr;
        }

        __syncthreads();  // all KPs reads done; safe to overwrite with P^T
#pragma unroll
        for (int i = 0; i < 4; i++)
#pragma unroll
            for (int j = 0; j < 4; j++)
                KPs[(tx * 4 + j) * LDT + ty * 4 + i] = p[i][j];
        __syncthreads();

        // O += P @ V : acc[i][j] += P[m][n] * V[n][dd], dd=tx*4+j
#pragma unroll 8
        for (int n = 0; n < 64; n++) {
            float4 pf = *(const float4*)&KPs[n * LDT + ty * 4];
            float4 vf = *(const float4*)&Vs[n * LDT + tx * 4];
            float pv[4] = {pf.x, pf.y, pf.z, pf.w};
            float vv[4] = {vf.x, vf.y, vf.z, vf.w};
#pragma unroll
            for (int i = 0; i < 4; i++)
#pragma unroll
                for (int j = 0; j < 4; j++)
                    acc[i][j] = fmaf(pv[i], vv[j], acc[i][j]);
        }
        __syncthreads();  // before next tile load overwrites KPs/Vs
    }

    // write normalized output to [token][h*64 + dd]
#pragma unroll
    for (int i = 0; i < 4; i++) {
        float inv = 1.f / lrow[i];
        size_t tok = tok_base + q0 + ty * 4 + i;
        float4 r;
        r.x = acc[i][0] * inv;
        r.y = acc[i][1] * inv;
        r.z = acc[i][2] * inv;
        r.w = acc[i][3] * inv;
        *(float4*)&out[tok * QKV_ + hcol + tx * 4] = r;
    }
}

// ---------------------------------------------------------------------------
extern "C" void kernel_launch(void* const* d_in, const int* in_sizes, int n_in,
                              void* d_out, int out_size)
{
    const float* x     = (const float*)d_in[0];  // [2,2048,1024]
    const float* w_qkv = (const float*)d_in[1];  // [3072,1024]
    const float* b_qkv = (const float*)d_in[2];  // [3072]
    const float* w_o   = (const float*)d_in[3];  // [1024,1024]
    const float* b_o   = (const float*)d_in[4];  // [1024]
    float* out = (float*)d_out;                  // [2,2048,1024]

    float *p_qkv, *p_att;
    cudaGetSymbolAddress((void**)&p_qkv, g_qkv);
    cudaGetSymbolAddress((void**)&p_att, g_att);

    static bool attr_done = false;
    // cudaFuncSetAttribute is idempotent & cheap; call every time (deterministic)
    cudaFuncSetAttribute(attn_kernel, cudaFuncAttributeMaxDynamicSharedMemorySize,
                         ATT_SMEM);
    (void)attr_done;

    // 1) QKV projection: [4096,3072] = x[4096,1024] @ w_qkv^T + b_qkv
    {
        dim3 grid(N_QKV / BN, M_TOK / BM);
        gemm_nt_bias<<<grid, 256>>>(x, w_qkv, b_qkv, p_qkv, M_TOK, N_QKV, HID);
    }

    // 2) attention -> g_att [4096,1024]
    {
        dim3 grid(S_ / 64, B_ * H_);
        attn_kernel<<<grid, 256, ATT_SMEM>>>(p_qkv, p_att);
    }

    // 3) output projection: out[4096,1024] = g_att @ w_o^T + b_o
    {
        dim3 grid(QKV_ / BN, M_TOK / BM);
        gemm_nt_bias<<<grid, 256>>>(p_att, w_o, b_o, out, M_TOK, QKV_, HID);
    }
}

// round 2
// speedup vs baseline: 1.1210x; 1.1210x over previous
#include <cuda_runtime.h>
#include <cuda_bf16.h>
#include <math.h>

// Problem constants (fixed shapes)
#define B_    2
#define S_    2048
#define H_    16
#define D_    64
#define HID   1024
#define QKV_  1024
#define M_TOK 4096
#define N_QKV 3072
#define SCALE 0.125f

// Scratch (device globals — no allocation allowed)
__device__ float g_qkv[(size_t)M_TOK * N_QKV];   // [token][3*QKV]
__device__ float g_att[(size_t)M_TOK * QKV_];    // [token][QKV]

// ---------------------------------------------------------------------------
// NT GEMM v2: C[M][N] = A[M][K]*B[N][K]^T + bias[N]
// 128x128 tile, BK=16, 256 threads, 8x8 microtile, double-buffered smem.
// ---------------------------------------------------------------------------
#define BM 128
#define BN 128
#define BK 16
#define LDA 132   // smem stride (floats)

__global__ __launch_bounds__(256) void gemm_nt_bias(
    const float* __restrict__ A,
    const float* __restrict__ B,
    const float* __restrict__ bias,
    float* __restrict__ C,
    int M, int N, int K)
{
    __shared__ float As[2][BK * LDA];  // As[k][m]
    __shared__ float Bs[2][BK * LDA];  // Bs[k][n]

    const int tid = threadIdx.x;
    const int tx  = tid & 15;
    const int ty  = tid >> 4;
    const int bm  = blockIdx.y * BM;
    const int bn  = blockIdx.x * BN;

    // LDG mapping: thread loads rows lrow and lrow+64, 4 consecutive k at lk
    const int lrow = tid >> 2;         // 0..63
    const int lk   = (tid & 3) << 2;   // 0,4,8,12

    const float* Ap = A + (size_t)(bm + lrow) * K + lk;
    const float* Bp = B + (size_t)(bn + lrow) * K + lk;
    const size_t rstep = (size_t)64 * K;

    float acc[8][8];
#pragma unroll
    for (int i = 0; i < 8; i++)
#pragma unroll
        for (int j = 0; j < 8; j++) acc[i][j] = 0.f;

    const int nch = K / BK;

    // prologue: chunk 0 -> buf 0
    {
        float4 a0 = *(const float4*)(Ap);
        float4 a1 = *(const float4*)(Ap + rstep);
        float4 b0 = *(const float4*)(Bp);
        float4 b1 = *(const float4*)(Bp + rstep);
        float av0[4] = {a0.x, a0.y, a0.z, a0.w};
        float av1[4] = {a1.x, a1.y, a1.z, a1.w};
        float bv0[4] = {b0.x, b0.y, b0.z, b0.w};
        float bv1[4] = {b1.x, b1.y, b1.z, b1.w};
#pragma unroll
        for (int i = 0; i < 4; i++) {
            As[0][(lk + i) * LDA + lrow]      = av0[i];
            As[0][(lk + i) * LDA + lrow + 64] = av1[i];
            Bs[0][(lk + i) * LDA + lrow]      = bv0[i];
            Bs[0][(lk + i) * LDA + lrow + 64] = bv1[i];
        }
    }
    __syncthreads();

    for (int c = 0; c < nch; c++) {
        const int buf = c & 1;
        float4 na0, na1, nb0, nb1;
        const bool more = (c + 1 < nch);
        if (more) {
            const float* Ap2 = Ap + (c + 1) * BK;
            const float* Bp2 = Bp + (c + 1) * BK;
            na0 = *(const float4*)(Ap2);
            na1 = *(const float4*)(Ap2 + rstep);
            nb0 = *(const float4*)(Bp2);
            nb1 = *(const float4*)(Bp2 + rstep);
        }

#pragma unroll
        for (int k = 0; k < BK; k++) {
            float4 a0 = *(const float4*)&As[buf][k * LDA + ty * 8];
            float4 a1 = *(const float4*)&As[buf][k * LDA + ty * 8 + 4];
            float4 b0 = *(const float4*)&Bs[buf][k * LDA + tx * 8];
            float4 b1 = *(const float4*)&Bs[buf][k * LDA + tx * 8 + 4];
            float av[8] = {a0.x, a0.y, a0.z, a0.w, a1.x, a1.y, a1.z, a1.w};
            float bv[8] = {b0.x, b0.y, b0.z, b0.w, b1.x, b1.y, b1.z, b1.w};
#pragma unroll
            for (int i = 0; i < 8; i++)
#pragma unroll
                for (int j = 0; j < 8; j++)
                    acc[i][j] = fmaf(av[i], bv[j], acc[i][j]);
        }

        if (more) {
            const int nb = buf ^ 1;
            float av0[4] = {na0.x, na0.y, na0.z, na0.w};
            float av1[4] = {na1.x, na1.y, na1.z, na1.w};
            float bv0[4] = {nb0.x, nb0.y, nb0.z, nb0.w};
            float bv1[4] = {nb1.x, nb1.y, nb1.z, nb1.w};
#pragma unroll
            for (int i = 0; i < 4; i++) {
                As[nb][(lk + i) * LDA + lrow]      = av0[i];
                As[nb][(lk + i) * LDA + lrow + 64] = av1[i];
                Bs[nb][(lk + i) * LDA + lrow]      = bv0[i];
                Bs[nb][(lk + i) * LDA + lrow + 64] = bv1[i];
            }
        }
        __syncthreads();
    }

    // epilogue: add bias, store
    float4 bb0 = *(const float4*)&bias[bn + tx * 8];
    float4 bb1 = *(const float4*)&bias[bn + tx * 8 + 4];
    float bb[8] = {bb0.x, bb0.y, bb0.z, bb0.w, bb1.x, bb1.y, bb1.z, bb1.w};
#pragma unroll
    for (int i = 0; i < 8; i++) {
        float* crow = C + (size_t)(bm + ty * 8 + i) * N + bn + tx * 8;
        float4 r0, r1;
        r0.x = acc[i][0] + bb[0]; r0.y = acc[i][1] + bb[1];
        r0.z = acc[i][2] + bb[2]; r0.w = acc[i][3] + bb[3];
        r1.x = acc[i][4] + bb[4]; r1.y = acc[i][5] + bb[5];
        r1.z = acc[i][6] + bb[6]; r1.w = acc[i][7] + bb[7];
        *(float4*)(crow)     = r0;
        *(float4*)(crow + 4) = r1;
    }
}

// ---------------------------------------------------------------------------
// Flash attention v2 (fp32). Block = (b,h) x 128-row q tile; k tiles of 128.
// 256 threads (16x16). Scores: 8x8 microtile. PV: 8x4 microtile.
// smem: Qs[d=64][m=128,ld132], KP union (Ks[d=64][n=128,ld136] / Ps[m=128][n=128,ld136]),
//       Vs[n=128][d=64,ld68]  => 138240 bytes, 1 CTA/SM.
// ---------------------------------------------------------------------------
#define QLD 132
#define KLD 136
#define PLD 136
#define VLD 68
#define ATT_SMEM ((64 * QLD + 128 * PLD + 128 * VLD) * 4)

__global__ __launch_bounds__(256) void attn_kernel(
    const float* __restrict__ qkv,  // [M_TOK][3*QKV]
    float* __restrict__ out)        // [M_TOK][QKV]
{
    extern __shared__ float sm[];
    float* Qs = sm;                  // Qs[d*QLD + m]
    float* KP = sm + 64 * QLD;       // Ks[d*KLD + n]  /  Ps[m*PLD + n]
    float* Vs = KP + 128 * PLD;      // Vs[n*VLD + d]

    const int tid = threadIdx.x;
    const int tx  = tid & 15;
    const int ty  = tid >> 4;
    const int qt  = blockIdx.x;      // 0..15
    const int bh  = blockIdx.y;      // 0..31
    const int b   = bh >> 4;
    const int h   = bh & 15;
    const int q0  = qt * 128;
    const size_t tok_base = (size_t)b * S_;
    const int hcol = h * D_;

    // load Q tile (transposed into Qs[d][m]) : 128 rows x 64 d
#pragma unroll
    for (int p = 0; p < 8; p++) {
        int idx = tid + p * 256;
        int m   = idx >> 4;
        int d4  = (idx & 15) << 2;
        float4 v = *(const float4*)&qkv[(tok_base + q0 + m) * (size_t)N_QKV + hcol + d4];
        Qs[(d4 + 0) * QLD + m] = v.x;
        Qs[(d4 + 1) * QLD + m] = v.y;
        Qs[(d4 + 2) * QLD + m] = v.z;
        Qs[(d4 + 3) * QLD + m] = v.w;
    }

    float o[8][4];
    float mrow[8], lrow[8];
#pragma unroll
    for (int i = 0; i < 8; i++) {
        mrow[i] = -INFINITY;
        lrow[i] = 0.f;
#pragma unroll
        for (int j = 0; j < 4; j++) o[i][j] = 0.f;
    }

    for (int kt = 0; kt < S_ / 128; kt++) {
        const int n0 = kt * 128;
        __syncthreads();  // prev iter PV reads of KP(P)/Vs done (also covers Q store on kt=0)

        // load K (transposed) and V (direct): 128 rows x 64 d each
#pragma unroll
        for (int p = 0; p < 8; p++) {
            int idx = tid + p * 256;
            int n   = idx >> 4;
            int d4  = (idx & 15) << 2;
            const float* rowp = qkv + (tok_base + n0 + n) * (size_t)N_QKV + hcol;
            float4 kv = *(const float4*)(rowp + QKV_ + d4);
            KP[(d4 + 0) * KLD + n] = kv.x;
            KP[(d4 + 1) * KLD + n] = kv.y;
            KP[(d4 + 2) * KLD + n] = kv.z;
            KP[(d4 + 3) * KLD + n] = kv.w;
            float4 vv = *(const float4*)(rowp + 2 * QKV_ + d4);
            *(float4*)&Vs[n * VLD + d4] = vv;
        }
        __syncthreads();

        // scores 128x128, 8x8 per thread
        float s[8][8];
#pragma unroll
        for (int i = 0; i < 8; i++)
#pragma unroll
            for (int j = 0; j < 8; j++) s[i][j] = 0.f;

#pragma unroll 4
        for (int d = 0; d < 64; d++) {
            float4 a0 = *(const float4*)&Qs[d * QLD + ty * 8];
            float4 a1 = *(const float4*)&Qs[d * QLD + ty * 8 + 4];
            float4 b0 = *(const float4*)&KP[d * KLD + tx * 8];
            float4 b1 = *(const float4*)&KP[d * KLD + tx * 8 + 4];
            float av[8] = {a0.x, a0.y, a0.z, a0.w, a1.x, a1.y, a1.z, a1.w};
            float bv[8] = {b0.x, b0.y, b0.z, b0.w, b1.x, b1.y, b1.z, b1.w};
#pragma unroll
            for (int i = 0; i < 8; i++)
#pragma unroll
                for (int j = 0; j < 8; j++)
                    s[i][j] = fmaf(av[i], bv[j], s[i][j]);
        }

        // online softmax (row stats replicated across 16 tx lanes in half-warp)
#pragma unroll
        for (int i = 0; i < 8; i++) {
            float rmax = -INFINITY;
#pragma unroll
            for (int j = 0; j < 8; j++) {
                s[i][j] *= SCALE;
                rmax = fmaxf(rmax, s[i][j]);
            }
#pragma unroll
            for (int off = 8; off > 0; off >>= 1)
                rmax = fmaxf(rmax, __shfl_xor_sync(0xffffffffu, rmax, off));
            float mnew = fmaxf(mrow[i], rmax);
            float corr = __expf(mrow[i] - mnew);
            float rsum = 0.f;
#pragma unroll
            for (int j = 0; j < 8; j++) {
                s[i][j] = __expf(s[i][j] - mnew);
                rsum += s[i][j];
            }
#pragma unroll
            for (int off = 8; off > 0; off >>= 1)
                rsum += __shfl_xor_sync(0xffffffffu, rsum, off);
            lrow[i] = lrow[i] * corr + rsum;
            mrow[i] = mnew;
#pragma unroll
            for (int j = 0; j < 4; j++) o[i][j] *= corr;
        }

        __syncthreads();  // all Ks reads done; reuse KP as P[m][n]
#pragma unroll
        for (int i = 0; i < 8; i++) {
            float4 p0, p1;
            p0.x = s[i][0]; p0.y = s[i][1]; p0.z = s[i][2]; p0.w = s[i][3];
            p1.x = s[i][4]; p1.y = s[i][5]; p1.z = s[i][6]; p1.w = s[i][7];
            float* prow = &KP[(ty * 8 + i) * PLD + tx * 8];
            *(float4*)(prow)     = p0;
            *(float4*)(prow + 4) = p1;
        }
        __syncthreads();

        // O += P @ V : o[i][j] over m=ty*8+i, d=tx*4+j, n-groups of 4
#pragma unroll 2
        for (int ng = 0; ng < 128; ng += 4) {
            float4 pf[8];
#pragma unroll
            for (int i = 0; i < 8; i++)
                pf[i] = *(const float4*)&KP[(ty * 8 + i) * PLD + ng];
            float4 vv[4];
#pragma unroll
            for (int jj = 0; jj < 4; jj++)
                vv[jj] = *(const float4*)&Vs[(ng + jj) * VLD + tx * 4];
#pragma unroll
            for (int i = 0; i < 8; i++) {
                float pv[4] = {pf[i].x, pf[i].y, pf[i].z, pf[i].w};
#pragma unroll
                for (int jj = 0; jj < 4; jj++) {
                    float vj[4] = {vv[jj].x, vv[jj].y, vv[jj].z, vv[jj].w};
#pragma unroll
                    for (int j = 0; j < 4; j++)
                        o[i][j] = fmaf(pv[jj], vj[j], o[i][j]);
                }
            }
        }
    }

    // write normalized output
#pragma unroll
    for (int i = 0; i < 8; i++) {
        float inv = 1.f / lrow[i];
        size_t tok = tok_base + q0 + ty * 8 + i;
        float4 r;
        r.x = o[i][0] * inv;
        r.y = o[i][1] * inv;
        r.z = o[i][2] * inv;
        r.w = o[i][3] * inv;
        *(float4*)&out[tok * QKV_ + hcol + tx * 4] = r;
    }
}

// ---------------------------------------------------------------------------
extern "C" void kernel_launch(void* const* d_in, const int* in_sizes, int n_in,
                              void* d_out, int out_size)
{
    const float* x     = (const float*)d_in[0];
    const float* w_qkv = (const float*)d_in[1];
    const float* b_qkv = (const float*)d_in[2];
    const float* w_o   = (const float*)d_in[3];
    const float* b_o   = (const float*)d_in[4];
    float* out = (float*)d_out;

    float *p_qkv, *p_att;
    cudaGetSymbolAddress((void**)&p_qkv, g_qkv);
    cudaGetSymbolAddress((void**)&p_att, g_att);

    cudaFuncSetAttribute(attn_kernel, cudaFuncAttributeMaxDynamicSharedMemorySize,
                         ATT_SMEM);

    // 1) QKV projection
    {
        dim3 grid(N_QKV / BN, M_TOK / BM);
        gemm_nt_bias<<<grid, 256>>>(x, w_qkv, b_qkv, p_qkv, M_TOK, N_QKV, HID);
    }
    // 2) attention
    {
        dim3 grid(S_ / 128, B_ * H_);
        attn_kernel<<<grid, 256, ATT_SMEM>>>(p_qkv, p_att);
    }
    // 3) output projection
    {
        dim3 grid(QKV_ / BN, M_TOK / BM);
        gemm_nt_bias<<<grid, 256>>>(p_att, w_o, b_o, out, M_TOK, QKV_, HID);
    }
}

// round 3
// speedup vs baseline: 1.1224x; 1.0012x over previous
#include <cuda_runtime.h>
#include <cuda_bf16.h>
#include <math.h>

// Problem constants (fixed shapes)
#define B_    2
#define S_    2048
#define H_    16
#define D_    64
#define HID   1024
#define QKV_  1024
#define M_TOK 4096
#define N_QKV 3072
#define SCALE 0.125f

typedef unsigned long long u64;

// packed f32x2 helpers (FFMA2 path — ptxas never emits this from C++)
__device__ __forceinline__ u64 pk2(float x, float y) {
    u64 r; asm("mov.b64 %0,{%1,%2};" : "=l"(r) : "f"(x), "f"(y)); return r;
}
__device__ __forceinline__ u64 bc2(float x) { return pk2(x, x); }
__device__ __forceinline__ void up2(u64 v, float& x, float& y) {
    asm("mov.b64 {%0,%1},%2;" : "=f"(x), "=f"(y) : "l"(v));
}
__device__ __forceinline__ u64 f2fma(u64 a, u64 b, u64 c) {
    u64 d; asm("fma.rn.f32x2 %0,%1,%2,%3;" : "=l"(d) : "l"(a), "l"(b), "l"(c)); return d;
}
__device__ __forceinline__ u64 f2add(u64 a, u64 b) {
    u64 d; asm("add.rn.f32x2 %0,%1,%2;" : "=l"(d) : "l"(a), "l"(b)); return d;
}
__device__ __forceinline__ u64 f2mul(u64 a, u64 b) {
    u64 d; asm("mul.rn.f32x2 %0,%1,%2;" : "=l"(d) : "l"(a), "l"(b)); return d;
}

// Scratch (device globals — no allocation allowed)
__device__ float g_qkv[(size_t)M_TOK * N_QKV];   // [token][3*QKV]
__device__ float g_att[(size_t)M_TOK * QKV_];    // [token][QKV]

// ---------------------------------------------------------------------------
// NT GEMM v3: C[M][N] = A[M][K]*B[N][K]^T + bias[N]
// 128x128 tile, BK=16, 256 threads, 8x8 microtile, FFMA2, double-buffered.
// ---------------------------------------------------------------------------
#define BM 128
#define BN 128
#define BK 16
#define LDA 132   // smem stride (floats)

__global__ __launch_bounds__(256) void gemm_nt_bias(
    const float* __restrict__ A,
    const float* __restrict__ B,
    const float* __restrict__ bias,
    float* __restrict__ C,
    int M, int N, int K)
{
    __shared__ float As[2][BK * LDA];  // As[k][m]
    __shared__ float Bs[2][BK * LDA];  // Bs[k][n]

    const int tid = threadIdx.x;
    const int tx  = tid & 15;
    const int ty  = tid >> 4;
    const int bm  = blockIdx.y * BM;
    const int bn  = blockIdx.x * BN;

    const int lrow = tid >> 2;         // 0..63
    const int lk   = (tid & 3) << 2;   // 0,4,8,12

    const float* Ap = A + (size_t)(bm + lrow) * K + lk;
    const float* Bp = B + (size_t)(bn + lrow) * K + lk;
    const size_t rstep = (size_t)64 * K;

    u64 acc2[8][4];
#pragma unroll
    for (int i = 0; i < 8; i++)
#pragma unroll
        for (int j = 0; j < 4; j++) acc2[i][j] = 0ull;

    const int nch = K / BK;

    // prologue: chunk 0 -> buf 0
    {
        float4 a0 = *(const float4*)(Ap);
        float4 a1 = *(const float4*)(Ap + rstep);
        float4 b0 = *(const float4*)(Bp);
        float4 b1 = *(const float4*)(Bp + rstep);
        float av0[4] = {a0.x, a0.y, a0.z, a0.w};
        float av1[4] = {a1.x, a1.y, a1.z, a1.w};
        float bv0[4] = {b0.x, b0.y, b0.z, b0.w};
        float bv1[4] = {b1.x, b1.y, b1.z, b1.w};
#pragma unroll
        for (int i = 0; i < 4; i++) {
            As[0][(lk + i) * LDA + lrow]      = av0[i];
            As[0][(lk + i) * LDA + lrow + 64] = av1[i];
            Bs[0][(lk + i) * LDA + lrow]      = bv0[i];
            Bs[0][(lk + i) * LDA + lrow + 64] = bv1[i];
        }
    }
    __syncthreads();

    for (int c = 0; c < nch; c++) {
        const int buf = c & 1;
        float4 na0, na1, nb0, nb1;
        const bool more = (c + 1 < nch);
        if (more) {
            const float* Ap2 = Ap + (c + 1) * BK;
            const float* Bp2 = Bp + (c + 1) * BK;
            na0 = *(const float4*)(Ap2);
            na1 = *(const float4*)(Ap2 + rstep);
            nb0 = *(const float4*)(Bp2);
            nb1 = *(const float4*)(Bp2 + rstep);
        }

#pragma unroll
        for (int k = 0; k < BK; k++) {
            float4 af0 = *(const float4*)&As[buf][k * LDA + ty * 8];
            float4 af1 = *(const float4*)&As[buf][k * LDA + ty * 8 + 4];
            ulonglong2 bq0 = *(const ulonglong2*)&Bs[buf][k * LDA + tx * 8];
            ulonglong2 bq1 = *(const ulonglong2*)&Bs[buf][k * LDA + tx * 8 + 4];
            u64 a2[8] = {bc2(af0.x), bc2(af0.y), bc2(af0.z), bc2(af0.w),
                         bc2(af1.x), bc2(af1.y), bc2(af1.z), bc2(af1.w)};
            u64 b2[4] = {bq0.x, bq0.y, bq1.x, bq1.y};
#pragma unroll
            for (int i = 0; i < 8; i++)
#pragma unroll
                for (int j = 0; j < 4; j++)
                    acc2[i][j] = f2fma(a2[i], b2[j], acc2[i][j]);
        }

        if (more) {
            const int nb = buf ^ 1;
            float av0[4] = {na0.x, na0.y, na0.z, na0.w};
            float av1[4] = {na1.x, na1.y, na1.z, na1.w};
            float bv0[4] = {nb0.x, nb0.y, nb0.z, nb0.w};
            float bv1[4] = {nb1.x, nb1.y, nb1.z, nb1.w};
#pragma unroll
            for (int i = 0; i < 4; i++) {
                As[nb][(lk + i) * LDA + lrow]      = av0[i];
                As[nb][(lk + i) * LDA + lrow + 64] = av1[i];
                Bs[nb][(lk + i) * LDA + lrow]      = bv0[i];
                Bs[nb][(lk + i) * LDA + lrow + 64] = bv1[i];
            }
        }
        __syncthreads();
    }

    // epilogue: packed bias add, packed stores
    ulonglong2 bbq0 = *(const ulonglong2*)&bias[bn + tx * 8];
    ulonglong2 bbq1 = *(const ulonglong2*)&bias[bn + tx * 8 + 4];
    u64 bb2[4] = {bbq0.x, bbq0.y, bbq1.x, bbq1.y};
#pragma unroll
    for (int i = 0; i < 8; i++) {
        float* crow = C + (size_t)(bm + ty * 8 + i) * N + bn + tx * 8;
        ulonglong2 w0, w1;
        w0.x = f2add(acc2[i][0], bb2[0]);
        w0.y = f2add(acc2[i][1], bb2[1]);
        w1.x = f2add(acc2[i][2], bb2[2]);
        w1.y = f2add(acc2[i][3], bb2[3]);
        *(ulonglong2*)(crow)     = w0;
        *(ulonglong2*)(crow + 4) = w1;
    }
}

// ---------------------------------------------------------------------------
// Flash attention v3 (fp32, FFMA2). Block = (b,h) x 128-row q tile; k tiles 128.
// 256 threads (16x16). smem ~135KB, 1 CTA/SM.
// ---------------------------------------------------------------------------
#define QLD 132
#define KLD 136
#define PLD 136
#define VLD 68
#define ATT_SMEM ((64 * QLD + 128 * PLD + 128 * VLD) * 4)

__global__ __launch_bounds__(256) void attn_kernel(
    const float* __restrict__ qkv,  // [M_TOK][3*QKV]
    float* __restrict__ out)        // [M_TOK][QKV]
{
    extern __shared__ float sm[];
    float* Qs = sm;                  // Qs[d*QLD + m]
    float* KP = sm + 64 * QLD;       // Ks[d*KLD + n]  /  Ps[m*PLD + n]
    float* Vs = KP + 128 * PLD;      // Vs[n*VLD + d]

    const int tid = threadIdx.x;
    const int tx  = tid & 15;
    const int ty  = tid >> 4;
    const int qt  = blockIdx.x;      // 0..15
    const int bh  = blockIdx.y;      // 0..31
    const int b   = bh >> 4;
    const int h   = bh & 15;
    const int q0  = qt * 128;
    const size_t tok_base = (size_t)b * S_;
    const int hcol = h * D_;

    // load Q tile (transposed into Qs[d][m])
#pragma unroll
    for (int p = 0; p < 8; p++) {
        int idx = tid + p * 256;
        int m   = idx >> 4;
        int d4  = (idx & 15) << 2;
        float4 v = *(const float4*)&qkv[(tok_base + q0 + m) * (size_t)N_QKV + hcol + d4];
        Qs[(d4 + 0) * QLD + m] = v.x;
        Qs[(d4 + 1) * QLD + m] = v.y;
        Qs[(d4 + 2) * QLD + m] = v.z;
        Qs[(d4 + 3) * QLD + m] = v.w;
    }

    u64 o2[8][2];            // packed along d
    float mrow[8], lrow[8];
#pragma unroll
    for (int i = 0; i < 8; i++) {
        mrow[i] = -INFINITY;
        lrow[i] = 0.f;
        o2[i][0] = 0ull;
        o2[i][1] = 0ull;
    }

    for (int kt = 0; kt < S_ / 128; kt++) {
        const int n0 = kt * 128;
        __syncthreads();  // prev PV reads done (covers Q store on kt=0)

        // load K (transposed) and V (direct)
#pragma unroll
        for (int p = 0; p < 8; p++) {
            int idx = tid + p * 256;
            int n   = idx >> 4;
            int d4  = (idx & 15) << 2;
            const float* rowp = qkv + (tok_base + n0 + n) * (size_t)N_QKV + hcol;
            float4 kv = *(const float4*)(rowp + QKV_ + d4);
            KP[(d4 + 0) * KLD + n] = kv.x;
            KP[(d4 + 1) * KLD + n] = kv.y;
            KP[(d4 + 2) * KLD + n] = kv.z;
            KP[(d4 + 3) * KLD + n] = kv.w;
            float4 vv = *(const float4*)(rowp + 2 * QKV_ + d4);
            *(float4*)&Vs[n * VLD + d4] = vv;
        }
        __syncthreads();

        // scores (packed along n): s2[i][j] = {s[i][2j], s[i][2j+1]}
        u64 s2[8][4];
#pragma unroll
        for (int i = 0; i < 8; i++)
#pragma unroll
            for (int j = 0; j < 4; j++) s2[i][j] = 0ull;

#pragma unroll 4
        for (int d = 0; d < 64; d++) {
            float4 af0 = *(const float4*)&Qs[d * QLD + ty * 8];
            float4 af1 = *(const float4*)&Qs[d * QLD + ty * 8 + 4];
            ulonglong2 kq0 = *(const ulonglong2*)&KP[d * KLD + tx * 8];
            ulonglong2 kq1 = *(const ulonglong2*)&KP[d * KLD + tx * 8 + 4];
            u64 a2[8] = {bc2(af0.x), bc2(af0.y), bc2(af0.z), bc2(af0.w),
                         bc2(af1.x), bc2(af1.y), bc2(af1.z), bc2(af1.w)};
            u64 b2[4] = {kq0.x, kq0.y, kq1.x, kq1.y};
#pragma unroll
            for (int i = 0; i < 8; i++)
#pragma unroll
                for (int j = 0; j < 4; j++)
                    s2[i][j] = f2fma(a2[i], b2[j], s2[i][j]);
        }

        __syncthreads();  // all K reads done; KP becomes P[m][n]

        // per-row softmax + P store
#pragma unroll
        for (int i = 0; i < 8; i++) {
            float sv[8];
            up2(s2[i][0], sv[0], sv[1]);
            up2(s2[i][1], sv[2], sv[3]);
            up2(s2[i][2], sv[4], sv[5]);
            up2(s2[i][3], sv[6], sv[7]);
            float rmax = -INFINITY;
#pragma unroll
            for (int j = 0; j < 8; j++) {
                sv[j] *= SCALE;
                rmax = fmaxf(rmax, sv[j]);
            }
#pragma unroll
            for (int off = 8; off > 0; off >>= 1)
                rmax = fmaxf(rmax, __shfl_xor_sync(0xffffffffu, rmax, off));
            float mnew = fmaxf(mrow[i], rmax);
            float corr = __expf(mrow[i] - mnew);
            float rsum = 0.f;
#pragma unroll
            for (int j = 0; j < 8; j++) {
                sv[j] = __expf(sv[j] - mnew);
                rsum += sv[j];
            }
#pragma unroll
            for (int off = 8; off > 0; off >>= 1)
                rsum += __shfl_xor_sync(0xffffffffu, rsum, off);
            lrow[i] = lrow[i] * corr + rsum;
            mrow[i] = mnew;
            u64 c2 = bc2(corr);
            o2[i][0] = f2mul(o2[i][0], c2);
            o2[i][1] = f2mul(o2[i][1], c2);
            float* prow = &KP[(ty * 8 + i) * PLD + tx * 8];
            float4 p0, p1;
            p0.x = sv[0]; p0.y = sv[1]; p0.z = sv[2]; p0.w = sv[3];
            p1.x = sv[4]; p1.y = sv[5]; p1.z = sv[6]; p1.w = sv[7];
            *(float4*)(prow)     = p0;
            *(float4*)(prow + 4) = p1;
        }
        __syncthreads();

        // O += P @ V : o2[i][j] over m=ty*8+i, d pairs at tx*4
#pragma unroll 2
        for (int ng = 0; ng < 128; ng += 4) {
            float4 pf[8];
#pragma unroll
            for (int i = 0; i < 8; i++)
                pf[i] = *(const float4*)&KP[(ty * 8 + i) * PLD + ng];
            u64 v2[4][2];
#pragma unroll
            for (int jj = 0; jj < 4; jj++) {
                ulonglong2 vq = *(const ulonglong2*)&Vs[(ng + jj) * VLD + tx * 4];
                v2[jj][0] = vq.x;
                v2[jj][1] = vq.y;
            }
#pragma unroll
            for (int i = 0; i < 8; i++) {
                u64 p0 = bc2(pf[i].x), p1 = bc2(pf[i].y);
                u64 p2 = bc2(pf[i].z), p3 = bc2(pf[i].w);
                o2[i][0] = f2fma(p0, v2[0][0], o2[i][0]);
                o2[i][1] = f2fma(p0, v2[0][1], o2[i][1]);
                o2[i][0] = f2fma(p1, v2[1][0], o2[i][0]);
                o2[i][1] = f2fma(p1, v2[1][1], o2[i][1]);
                o2[i][0] = f2fma(p2, v2[2][0], o2[i][0]);
                o2[i][1] = f2fma(p2, v2[2][1], o2[i][1]);
                o2[i][0] = f2fma(p3, v2[3][0], o2[i][0]);
                o2[i][1] = f2fma(p3, v2[3][1], o2[i][1]);
            }
        }
    }

    // write normalized output (packed)
#pragma unroll
    for (int i = 0; i < 8; i++) {
        u64 inv2 = bc2(1.f / lrow[i]);
        size_t tok = tok_base + q0 + ty * 8 + i;
        ulonglong2 w;
        w.x = f2mul(o2[i][0], inv2);
        w.y = f2mul(o2[i][1], inv2);
        *(ulonglong2*)&out[tok * QKV_ + hcol + tx * 4] = w;
    }
}

// ---------------------------------------------------------------------------
extern "C" void kernel_launch(void* const* d_in, const int* in_sizes, int n_in,
                              void* d_out, int out_size)
{
    const float* x     = (const float*)d_in[0];
    const float* w_qkv = (const float*)d_in[1];
    const float* b_qkv = (const float*)d_in[2];
    const float* w_o   = (const float*)d_in[3];
    const float* b_o   = (const float*)d_in[4];
    float* out = (float*)d_out;

    float *p_qkv, *p_att;
    cudaGetSymbolAddress((void**)&p_qkv, g_qkv);
    cudaGetSymbolAddress((void**)&p_att, g_att);

    cudaFuncSetAttribute(attn_kernel, cudaFuncAttributeMaxDynamicSharedMemorySize,
                         ATT_SMEM);

    // 1) QKV projection
    {
        dim3 grid(N_QKV / BN, M_TOK / BM);
        gemm_nt_bias<<<grid, 256>>>(x, w_qkv, b_qkv, p_qkv, M_TOK, N_QKV, HID);
    }
    // 2) attention
    {
        dim3 grid(S_ / 128, B_ * H_);
        attn_kernel<<<grid, 256, ATT_SMEM>>>(p_qkv, p_att);
    }
    // 3) output projection
    {
        dim3 grid(QKV_ / BN, M_TOK / BM);
        gemm_nt_bias<<<grid, 256>>>(p_att, w_o, b_o, out, M_TOK, QKV_, HID);
    }
}

// round 5
// speedup vs baseline: 1.2990x; 1.1574x over previous
#include <cuda_runtime.h>
#include <cuda_bf16.h>
#include <math.h>
#include <stdint.h>

// Problem constants (fixed shapes)
#define B_    2
#define S_    2048
#define H_    16
#define D_    64
#define HID   1024
#define QKV_  1024
#define M_TOK 4096
#define N_QKV 3072
#define SCALE 0.125f

typedef unsigned long long u64;

// ---------------- packed f32x2 helpers (attention kernel) ------------------
__device__ __forceinline__ u64 pk2(float x, float y) {
    u64 r; asm("mov.b64 %0,{%1,%2};" : "=l"(r) : "f"(x), "f"(y)); return r;
}
__device__ __forceinline__ u64 bc2(float x) { return pk2(x, x); }
__device__ __forceinline__ void up2(u64 v, float& x, float& y) {
    asm("mov.b64 {%0,%1},%2;" : "=f"(x), "=f"(y) : "l"(v));
}
__device__ __forceinline__ u64 f2fma(u64 a, u64 b, u64 c) {
    u64 d; asm("fma.rn.f32x2 %0,%1,%2,%3;" : "=l"(d) : "l"(a), "l"(b), "l"(c)); return d;
}
__device__ __forceinline__ u64 f2mul(u64 a, u64 b) {
    u64 d; asm("mul.rn.f32x2 %0,%1,%2;" : "=l"(d) : "l"(a), "l"(b)); return d;
}

// ---------------- bf16 helpers ----------------------------------------------
__device__ __forceinline__ uint32_t pkbf(__nv_bfloat16 x, __nv_bfloat16 y) {
    __nv_bfloat162 t; t.x = x; t.y = y;
    return *(uint32_t*)&t;
}

// mma.sync m16n8k16 row.col f32.bf16.bf16.f32, acc in place
__device__ __forceinline__ void mma16816(float* d, const uint32_t* a, const uint32_t* b) {
    asm volatile(
        "mma.sync.aligned.m16n8k16.row.col.f32.bf16.bf16.f32 "
        "{%0,%1,%2,%3},{%4,%5,%6,%7},{%8,%9},{%0,%1,%2,%3};"
        : "+f"(d[0]), "+f"(d[1]), "+f"(d[2]), "+f"(d[3])
        : "r"(a[0]), "r"(a[1]), "r"(a[2]), "r"(a[3]), "r"(b[0]), "r"(b[1]));
}

// Scratch (device globals — no allocation allowed)
__device__ float g_qkv[(size_t)M_TOK * N_QKV];   // [token][3*QKV]
__device__ float g_att[(size_t)M_TOK * QKV_];    // [token][QKV]

// ---------------------------------------------------------------------------
// Tensor-core NT GEMM: C[M][N] = A[M][K]*B[N][K]^T + bias[N]   (fp32 in/out)
// bf16 2-term split: D += Ah*Bh + Ah*Bl + Al*Bh  (fp32 accumulate)
// CTA tile 128x128, BK=32, 8 warps (warp tile 64x32), double-buffered smem.
// smem layout per stage (bf16, ld=36): AH[128][36] AL BH BL  (9216 B each)
// ---------------------------------------------------------------------------
#define GLD 36                           // smem row stride in bf16 elems
#define MAT_B (128 * GLD * 2)            // 9216 bytes per matrix tile
#define STAGE_B (4 * MAT_B)              // 36864
#define GEMM_SMEM (2 * STAGE_B)          // 73728

__global__ __launch_bounds__(256) void gemm_tc(
    const float* __restrict__ A,
    const float* __restrict__ B,
    const float* __restrict__ bias,
    float* __restrict__ C,
    int M, int N, int K)
{
    extern __shared__ char smem[];

    const int tid = threadIdx.x;
    const int wid = tid >> 5;
    const int lid = tid & 31;
    const int g   = lid >> 2;      // 0..7
    const int tg  = lid & 3;       // 0..3
    const int wm  = (wid & 1) * 64;
    const int wn  = (wid >> 1) * 32;
    const int bm  = blockIdx.y * 128;
    const int bn  = blockIdx.x * 128;

    // loader mapping: row = tid/2 (0..127), col half = (tid&1)*16
    const int lr = tid >> 1;
    const int lc = (tid & 1) << 4;
    const float* Ap = A + (size_t)(bm + lr) * K + lc;
    const float* Bp = B + (size_t)(bn + lr) * K + lc;

    float acc[4][4][4];
#pragma unroll
    for (int mi = 0; mi < 4; mi++)
#pragma unroll
        for (int ni = 0; ni < 4; ni++)
#pragma unroll
            for (int r = 0; r < 4; r++) acc[mi][ni][r] = 0.f;

    const int nch = K / 32;

    // conversion+store of one chunk held in regs
    auto store_chunk = [&](int buf, const float4* va, const float4* vb) {
        __nv_bfloat16* AH = (__nv_bfloat16*)(smem + buf * STAGE_B);
        __nv_bfloat16* AL = (__nv_bfloat16*)(smem + buf * STAGE_B + MAT_B);
        __nv_bfloat16* BH = (__nv_bfloat16*)(smem + buf * STAGE_B + 2 * MAT_B);
        __nv_bfloat16* BL = (__nv_bfloat16*)(smem + buf * STAGE_B + 3 * MAT_B);
        const int base = lr * GLD + lc;
#pragma unroll
        for (int j = 0; j < 4; j++) {
            float4 a = va[j];
            __nv_bfloat16 hx = __float2bfloat16(a.x), hy = __float2bfloat16(a.y);
            __nv_bfloat16 hz = __float2bfloat16(a.z), hw = __float2bfloat16(a.w);
            __nv_bfloat16 lx = __float2bfloat16(a.x - __bfloat162float(hx));
            __nv_bfloat16 ly = __float2bfloat16(a.y - __bfloat162float(hy));
            __nv_bfloat16 lz = __float2bfloat16(a.z - __bfloat162float(hz));
            __nv_bfloat16 lw = __float2bfloat16(a.w - __bfloat162float(hw));
            *(uint32_t*)&AH[base + j * 4]     = pkbf(hx, hy);
            *(uint32_t*)&AH[base + j * 4 + 2] = pkbf(hz, hw);
            *(uint32_t*)&AL[base + j * 4]     = pkbf(lx, ly);
            *(uint32_t*)&AL[base + j * 4 + 2] = pkbf(lz, lw);

            float4 b = vb[j];
            __nv_bfloat16 px = __float2bfloat16(b.x), py = __float2bfloat16(b.y);
            __nv_bfloat16 pz = __float2bfloat16(b.z), pw = __float2bfloat16(b.w);
            __nv_bfloat16 qx = __float2bfloat16(b.x - __bfloat162float(px));
            __nv_bfloat16 qy = __float2bfloat16(b.y - __bfloat162float(py));
            __nv_bfloat16 qz = __float2bfloat16(b.z - __bfloat162float(pz));
            __nv_bfloat16 qw = __float2bfloat16(b.w - __bfloat162float(pw));
            *(uint32_t*)&BH[base + j * 4]     = pkbf(px, py);
            *(uint32_t*)&BH[base + j * 4 + 2] = pkbf(pz, pw);
            *(uint32_t*)&BL[base + j * 4]     = pkbf(qx, qy);
            *(uint32_t*)&BL[base + j * 4 + 2] = pkbf(qz, qw);
        }
    };

    // prologue: chunk 0 -> buf 0
    {
        float4 va[4], vb[4];
#pragma unroll
        for (int j = 0; j < 4; j++) {
            va[j] = *(const float4*)(Ap + j * 4);
            vb[j] = *(const float4*)(Bp + j * 4);
        }
        store_chunk(0, va, vb);
    }
    __syncthreads();

    for (int c = 0; c < nch; c++) {
        const int buf = c & 1;
        float4 va[4], vb[4];
        const bool more = (c + 1 < nch);
        if (more) {
            const float* Ap2 = Ap + (c + 1) * 32;
            const float* Bp2 = Bp + (c + 1) * 32;
#pragma unroll
            for (int j = 0; j < 4; j++) {
                va[j] = *(const float4*)(Ap2 + j * 4);
                vb[j] = *(const float4*)(Bp2 + j * 4);
            }
        }

        const __nv_bfloat16* AH = (const __nv_bfloat16*)(smem + buf * STAGE_B);
        const __nv_bfloat16* AL = (const __nv_bfloat16*)(smem + buf * STAGE_B + MAT_B);
        const __nv_bfloat16* BH = (const __nv_bfloat16*)(smem + buf * STAGE_B + 2 * MAT_B);
        const __nv_bfloat16* BL = (const __nv_bfloat16*)(smem + buf * STAGE_B + 3 * MAT_B);

#pragma unroll
        for (int k2 = 0; k2 < 2; k2++) {
            const int kb = k2 * 16 + tg * 2;
            uint32_t bh[4][2], bl[4][2];
#pragma unroll
            for (int ni = 0; ni < 4; ni++) {
                const int n = wn + ni * 8 + g;
                bh[ni][0] = *(const uint32_t*)&BH[n * GLD + kb];
                bh[ni][1] = *(const uint32_t*)&BH[n * GLD + kb + 8];
                bl[ni][0] = *(const uint32_t*)&BL[n * GLD + kb];
                bl[ni][1] = *(const uint32_t*)&BL[n * GLD + kb + 8];
            }
#pragma unroll
            for (int mi = 0; mi < 4; mi++) {
                const int r0 = wm + mi * 16 + g;
                uint32_t ah[4], al[4];
                ah[0] = *(const uint32_t*)&AH[r0 * GLD + kb];
                ah[1] = *(const uint32_t*)&AH[(r0 + 8) * GLD + kb];
                ah[2] = *(const uint32_t*)&AH[r0 * GLD + kb + 8];
                ah[3] = *(const uint32_t*)&AH[(r0 + 8) * GLD + kb + 8];
                al[0] = *(const uint32_t*)&AL[r0 * GLD + kb];
                al[1] = *(const uint32_t*)&AL[(r0 + 8) * GLD + kb];
                al[2] = *(const uint32_t*)&AL[r0 * GLD + kb + 8];
                al[3] = *(const uint32_t*)&AL[(r0 + 8) * GLD + kb + 8];
#pragma unroll
                for (int ni = 0; ni < 4; ni++) {
                    mma16816(acc[mi][ni], ah, bh[ni]);
                    mma16816(acc[mi][ni], ah, bl[ni]);
                    mma16816(acc[mi][ni], al, bh[ni]);
                }
            }
        }

        __syncthreads();
        if (more) {
            store_chunk(buf ^ 1, va, vb);
        }
        __syncthreads();
    }

    // epilogue: add bias, store (thread owns rows g,g+8; cols tg*2,tg*2+1 per tile)
#pragma unroll
    for (int ni = 0; ni < 4; ni++) {
        const int col = bn + wn + ni * 8 + tg * 2;
        const float bx = bias[col], by = bias[col + 1];
#pragma unroll
        for (int mi = 0; mi < 4; mi++) {
            const int row = bm + wm + mi * 16 + g;
            float2 w0, w1;
            w0.x = acc[mi][ni][0] + bx;
            w0.y = acc[mi][ni][1] + by;
            w1.x = acc[mi][ni][2] + bx;
            w1.y = acc[mi][ni][3] + by;
            *(float2*)&C[(size_t)row * N + col]       = w0;
            *(float2*)&C[(size_t)(row + 8) * N + col] = w1;
        }
    }
}

// ---------------------------------------------------------------------------
// Flash attention (fp32, FFMA2) — unchanged from round 3 (passing)
// ---------------------------------------------------------------------------
#define QLD 132
#define KLD 136
#define PLD 136
#define VLD 68
#define ATT_SMEM ((64 * QLD + 128 * PLD + 128 * VLD) * 4)

__global__ __launch_bounds__(256) void attn_kernel(
    const float* __restrict__ qkv,
    float* __restrict__ out)
{
    extern __shared__ float sm[];
    float* Qs = sm;
    float* KP = sm + 64 * QLD;
    float* Vs = KP + 128 * PLD;

    const int tid = threadIdx.x;
    const int tx  = tid & 15;
    const int ty  = tid >> 4;
    const int qt  = blockIdx.x;
    const int bh  = blockIdx.y;
    const int b   = bh >> 4;
    const int h   = bh & 15;
    const int q0  = qt * 128;
    const size_t tok_base = (size_t)b * S_;
    const int hcol = h * D_;

#pragma unroll
    for (int p = 0; p < 8; p++) {
        int idx = tid + p * 256;
        int m   = idx >> 4;
        int d4  = (idx & 15) << 2;
        float4 v = *(const float4*)&qkv[(tok_base + q0 + m) * (size_t)N_QKV + hcol + d4];
        Qs[(d4 + 0) * QLD + m] = v.x;
        Qs[(d4 + 1) * QLD + m] = v.y;
        Qs[(d4 + 2) * QLD + m] = v.z;
        Qs[(d4 + 3) * QLD + m] = v.w;
    }

    u64 o2[8][2];
    float mrow[8], lrow[8];
#pragma unroll
    for (int i = 0; i < 8; i++) {
        mrow[i] = -INFINITY; lrow[i] = 0.f; o2[i][0] = 0ull; o2[i][1] = 0ull;
    }

    for (int kt = 0; kt < S_ / 128; kt++) {
        const int n0 = kt * 128;
        __syncthreads();
#pragma unroll
        for (int p = 0; p < 8; p++) {
            int idx = tid + p * 256;
            int n   = idx >> 4;
            int d4  = (idx & 15) << 2;
            const float* rowp = qkv + (tok_base + n0 + n) * (size_t)N_QKV + hcol;
            float4 kv = *(const float4*)(rowp + QKV_ + d4);
            KP[(d4 + 0) * KLD + n] = kv.x;
            KP[(d4 + 1) * KLD + n] = kv.y;
            KP[(d4 + 2) * KLD + n] = kv.z;
            KP[(d4 + 3) * KLD + n] = kv.w;
            float4 vv = *(const float4*)(rowp + 2 * QKV_ + d4);
            *(float4*)&Vs[n * VLD + d4] = vv;
        }
        __syncthreads();

        u64 s2[8][4];
#pragma unroll
        for (int i = 0; i < 8; i++)
#pragma unroll
            for (int j = 0; j < 4; j++) s2[i][j] = 0ull;

#pragma unroll 4
        for (int d = 0; d < 64; d++) {
            float4 af0 = *(const float4*)&Qs[d * QLD + ty * 8];
            float4 af1 = *(const float4*)&Qs[d * QLD + ty * 8 + 4];
            ulonglong2 kq0 = *(const ulonglong2*)&KP[d * KLD + tx * 8];
            ulonglong2 kq1 = *(const ulonglong2*)&KP[d * KLD + tx * 8 + 4];
            u64 a2[8] = {bc2(af0.x), bc2(af0.y), bc2(af0.z), bc2(af0.w),
                         bc2(af1.x), bc2(af1.y), bc2(af1.z), bc2(af1.w)};
            u64 b2[4] = {kq0.x, kq0.y, kq1.x, kq1.y};
#pragma unroll
            for (int i = 0; i < 8; i++)
#pragma unroll
                for (int j = 0; j < 4; j++)
                    s2[i][j] = f2fma(a2[i], b2[j], s2[i][j]);
        }

        __syncthreads();

#pragma unroll
        for (int i = 0; i < 8; i++) {
            float sv[8];
            up2(s2[i][0], sv[0], sv[1]);
            up2(s2[i][1], sv[2], sv[3]);
            up2(s2[i][2], sv[4], sv[5]);
            up2(s2[i][3], sv[6], sv[7]);
            float rmax = -INFINITY;
#pragma unroll
            for (int j = 0; j < 8; j++) { sv[j] *= SCALE; rmax = fmaxf(rmax, sv[j]); }
#pragma unroll
            for (int off = 8; off > 0; off >>= 1)
                rmax = fmaxf(rmax, __shfl_xor_sync(0xffffffffu, rmax, off));
            float mnew = fmaxf(mrow[i], rmax);
            float corr = __expf(mrow[i] - mnew);
            float rsum = 0.f;
#pragma unroll
            for (int j = 0; j < 8; j++) { sv[j] = __expf(sv[j] - mnew); rsum += sv[j]; }
#pragma unroll
            for (int off = 8; off > 0; off >>= 1)
                rsum += __shfl_xor_sync(0xffffffffu, rsum, off);
            lrow[i] = lrow[i] * corr + rsum;
            mrow[i] = mnew;
            u64 c2 = bc2(corr);
            o2[i][0] = f2mul(o2[i][0], c2);
            o2[i][1] = f2mul(o2[i][1], c2);
            float* prow = &KP[(ty * 8 + i) * PLD + tx * 8];
            float4 p0, p1;
            p0.x = sv[0]; p0.y = sv[1]; p0.z = sv[2]; p0.w = sv[3];
            p1.x = sv[4]; p1.y = sv[5]; p1.z = sv[6]; p1.w = sv[7];
            *(float4*)(prow)     = p0;
            *(float4*)(prow + 4) = p1;
        }
        __syncthreads();

#pragma unroll 2
        for (int ng = 0; ng < 128; ng += 4) {
            float4 pf[8];
#pragma unroll
            for (int i = 0; i < 8; i++)
                pf[i] = *(const float4*)&KP[(ty * 8 + i) * PLD + ng];
            u64 v2[4][2];
#pragma unroll
            for (int jj = 0; jj < 4; jj++) {
                ulonglong2 vq = *(const ulonglong2*)&Vs[(ng + jj) * VLD + tx * 4];
                v2[jj][0] = vq.x;
                v2[jj][1] = vq.y;
            }
#pragma unroll
            for (int i = 0; i < 8; i++) {
                u64 p0 = bc2(pf[i].x), p1 = bc2(pf[i].y);
                u64 p2 = bc2(pf[i].z), p3 = bc2(pf[i].w);
                o2[i][0] = f2fma(p0, v2[0][0], o2[i][0]);
                o2[i][1] = f2fma(p0, v2[0][1], o2[i][1]);
                o2[i][0] = f2fma(p1, v2[1][0], o2[i][0]);
                o2[i][1] = f2fma(p1, v2[1][1], o2[i][1]);
                o2[i][0] = f2fma(p2, v2[2][0], o2[i][0]);
                o2[i][1] = f2fma(p2, v2[2][1], o2[i][1]);
                o2[i][0] = f2fma(p3, v2[3][0], o2[i][0]);
                o2[i][1] = f2fma(p3, v2[3][1], o2[i][1]);
            }
        }
    }

#pragma unroll
    for (int i = 0; i < 8; i++) {
        u64 inv2 = bc2(1.f / lrow[i]);
        size_t tok = tok_base + q0 + ty * 8 + i;
        ulonglong2 w;
        w.x = f2mul(o2[i][0], inv2);
        w.y = f2mul(o2[i][1], inv2);
        *(ulonglong2*)&out[tok * QKV_ + hcol + tx * 4] = w;
    }
}

// ---------------------------------------------------------------------------
extern "C" void kernel_launch(void* const* d_in, const int* in_sizes, int n_in,
                              void* d_out, int out_size)
{
    const float* x     = (const float*)d_in[0];
    const float* w_qkv = (const float*)d_in[1];
    const float* b_qkv = (const float*)d_in[2];
    const float* w_o   = (const float*)d_in[3];
    const float* b_o   = (const float*)d_in[4];
    float* out = (float*)d_out;

    float *p_qkv, *p_att;
    cudaGetSymbolAddress((void**)&p_qkv, g_qkv);
    cudaGetSymbolAddress((void**)&p_att, g_att);

    cudaFuncSetAttribute(gemm_tc, cudaFuncAttributeMaxDynamicSharedMemorySize,
                         GEMM_SMEM);
    cudaFuncSetAttribute(attn_kernel, cudaFuncAttributeMaxDynamicSharedMemorySize,
                         ATT_SMEM);

    // 1) QKV projection: [4096,3072]
    {
        dim3 grid(N_QKV / 128, M_TOK / 128);
        gemm_tc<<<grid, 256, GEMM_SMEM>>>(x, w_qkv, b_qkv, p_qkv, M_TOK, N_QKV, HID);
    }
    // 2) attention
    {
        dim3 grid(S_ / 128, B_ * H_);
        attn_kernel<<<grid, 256, ATT_SMEM>>>(p_qkv, p_att);
    }
    // 3) output projection: [4096,1024]
    {
        dim3 grid(QKV_ / 128, M_TOK / 128);
        gemm_tc<<<grid, 256, GEMM_SMEM>>>(p_att, w_o, b_o, out, M_TOK, QKV_, HID);
    }
}

// round 6
// speedup vs baseline: 1.8474x; 1.4222x over previous
#include <cuda_runtime.h>
#include <cuda_bf16.h>
#include <math.h>
#include <stdint.h>

// Problem constants (fixed shapes)
#define B_    2
#define S_    2048
#define H_    16
#define D_    64
#define HID   1024
#define QKV_  1024
#define M_TOK 4096
#define N_QKV 3072
#define SCALE 0.125f

typedef unsigned long long u64;

// ---------------- bf16 helpers ----------------------------------------------
__device__ __forceinline__ uint32_t pkbf(__nv_bfloat16 x, __nv_bfloat16 y) {
    __nv_bfloat162 t; t.x = x; t.y = y;
    return *(uint32_t*)&t;
}
// split pair (x,y) into bf16 hi pair (returned) and lo pair (out param)
__device__ __forceinline__ uint32_t splitp(float x, float y, uint32_t& lo) {
    __nv_bfloat16 hx = __float2bfloat16(x), hy = __float2bfloat16(y);
    __nv_bfloat16 lx = __float2bfloat16(x - __bfloat162float(hx));
    __nv_bfloat16 ly = __float2bfloat16(y - __bfloat162float(hy));
    lo = pkbf(lx, ly);
    return pkbf(hx, hy);
}

// mma.sync m16n8k16 row.col f32.bf16.bf16.f32, acc in place
__device__ __forceinline__ void mma16816(float* d, const uint32_t* a, const uint32_t* b) {
    asm volatile(
        "mma.sync.aligned.m16n8k16.row.col.f32.bf16.bf16.f32 "
        "{%0,%1,%2,%3},{%4,%5,%6,%7},{%8,%9},{%0,%1,%2,%3};"
        : "+f"(d[0]), "+f"(d[1]), "+f"(d[2]), "+f"(d[3])
        : "r"(a[0]), "r"(a[1]), "r"(a[2]), "r"(a[3]), "r"(b[0]), "r"(b[1]));
}

// Scratch (device globals — no allocation allowed)
__device__ float g_qkv[(size_t)M_TOK * N_QKV];   // [token][3*QKV]
__device__ float g_att[(size_t)M_TOK * QKV_];    // [token][QKV]

// ---------------------------------------------------------------------------
// Tensor-core NT GEMM (round-5, passing): C = A*B^T + bias, bf16 2-term split.
// ---------------------------------------------------------------------------
#define GLD 36
#define MAT_B (128 * GLD * 2)
#define STAGE_B (4 * MAT_B)
#define GEMM_SMEM (2 * STAGE_B)

__global__ __launch_bounds__(256) void gemm_tc(
    const float* __restrict__ A,
    const float* __restrict__ B,
    const float* __restrict__ bias,
    float* __restrict__ C,
    int M, int N, int K)
{
    extern __shared__ char smem[];

    const int tid = threadIdx.x;
    const int wid = tid >> 5;
    const int lid = tid & 31;
    const int g   = lid >> 2;
    const int tg  = lid & 3;
    const int wm  = (wid & 1) * 64;
    const int wn  = (wid >> 1) * 32;
    const int bm  = blockIdx.y * 128;
    const int bn  = blockIdx.x * 128;

    const int lr = tid >> 1;
    const int lc = (tid & 1) << 4;
    const float* Ap = A + (size_t)(bm + lr) * K + lc;
    const float* Bp = B + (size_t)(bn + lr) * K + lc;

    float acc[4][4][4];
#pragma unroll
    for (int mi = 0; mi < 4; mi++)
#pragma unroll
        for (int ni = 0; ni < 4; ni++)
#pragma unroll
            for (int r = 0; r < 4; r++) acc[mi][ni][r] = 0.f;

    const int nch = K / 32;

    auto store_chunk = [&](int buf, const float4* va, const float4* vb) {
        __nv_bfloat16* AH = (__nv_bfloat16*)(smem + buf * STAGE_B);
        __nv_bfloat16* AL = (__nv_bfloat16*)(smem + buf * STAGE_B + MAT_B);
        __nv_bfloat16* BH = (__nv_bfloat16*)(smem + buf * STAGE_B + 2 * MAT_B);
        __nv_bfloat16* BL = (__nv_bfloat16*)(smem + buf * STAGE_B + 3 * MAT_B);
        const int base = lr * GLD + lc;
#pragma unroll
        for (int j = 0; j < 4; j++) {
            float4 a = va[j];
            uint32_t lo0, lo1;
            uint32_t hi0 = splitp(a.x, a.y, lo0);
            uint32_t hi1 = splitp(a.z, a.w, lo1);
            *(uint32_t*)&AH[base + j * 4]     = hi0;
            *(uint32_t*)&AH[base + j * 4 + 2] = hi1;
            *(uint32_t*)&AL[base + j * 4]     = lo0;
            *(uint32_t*)&AL[base + j * 4 + 2] = lo1;

            float4 b = vb[j];
            uint32_t ql0, ql1;
            uint32_t qh0 = splitp(b.x, b.y, ql0);
            uint32_t qh1 = splitp(b.z, b.w, ql1);
            *(uint32_t*)&BH[base + j * 4]     = qh0;
            *(uint32_t*)&BH[base + j * 4 + 2] = qh1;
            *(uint32_t*)&BL[base + j * 4]     = ql0;
            *(uint32_t*)&BL[base + j * 4 + 2] = ql1;
        }
    };

    {
        float4 va[4], vb[4];
#pragma unroll
        for (int j = 0; j < 4; j++) {
            va[j] = *(const float4*)(Ap + j * 4);
            vb[j] = *(const float4*)(Bp + j * 4);
        }
        store_chunk(0, va, vb);
    }
    __syncthreads();

    for (int c = 0; c < nch; c++) {
        const int buf = c & 1;
        float4 va[4], vb[4];
        const bool more = (c + 1 < nch);
        if (more) {
            const float* Ap2 = Ap + (c + 1) * 32;
            const float* Bp2 = Bp + (c + 1) * 32;
#pragma unroll
            for (int j = 0; j < 4; j++) {
                va[j] = *(const float4*)(Ap2 + j * 4);
                vb[j] = *(const float4*)(Bp2 + j * 4);
            }
        }

        const __nv_bfloat16* AH = (const __nv_bfloat16*)(smem + buf * STAGE_B);
        const __nv_bfloat16* AL = (const __nv_bfloat16*)(smem + buf * STAGE_B + MAT_B);
        const __nv_bfloat16* BH = (const __nv_bfloat16*)(smem + buf * STAGE_B + 2 * MAT_B);
        const __nv_bfloat16* BL = (const __nv_bfloat16*)(smem + buf * STAGE_B + 3 * MAT_B);

#pragma unroll
        for (int k2 = 0; k2 < 2; k2++) {
            const int kb = k2 * 16 + tg * 2;
            uint32_t bhf[4][2], blf[4][2];
#pragma unroll
            for (int ni = 0; ni < 4; ni++) {
                const int n = wn + ni * 8 + g;
                bhf[ni][0] = *(const uint32_t*)&BH[n * GLD + kb];
                bhf[ni][1] = *(const uint32_t*)&BH[n * GLD + kb + 8];
                blf[ni][0] = *(const uint32_t*)&BL[n * GLD + kb];
                blf[ni][1] = *(const uint32_t*)&BL[n * GLD + kb + 8];
            }
#pragma unroll
            for (int mi = 0; mi < 4; mi++) {
                const int r0 = wm + mi * 16 + g;
                uint32_t ah[4], al[4];
                ah[0] = *(const uint32_t*)&AH[r0 * GLD + kb];
                ah[1] = *(const uint32_t*)&AH[(r0 + 8) * GLD + kb];
                ah[2] = *(const uint32_t*)&AH[r0 * GLD + kb + 8];
                ah[3] = *(const uint32_t*)&AH[(r0 + 8) * GLD + kb + 8];
                al[0] = *(const uint32_t*)&AL[r0 * GLD + kb];
                al[1] = *(const uint32_t*)&AL[(r0 + 8) * GLD + kb];
                al[2] = *(const uint32_t*)&AL[r0 * GLD + kb + 8];
                al[3] = *(const uint32_t*)&AL[(r0 + 8) * GLD + kb + 8];
#pragma unroll
                for (int ni = 0; ni < 4; ni++) {
                    mma16816(acc[mi][ni], ah, bhf[ni]);
                    mma16816(acc[mi][ni], ah, blf[ni]);
                    mma16816(acc[mi][ni], al, bhf[ni]);
                }
            }
        }

        __syncthreads();
        if (more) store_chunk(buf ^ 1, va, vb);
        __syncthreads();
    }

#pragma unroll
    for (int ni = 0; ni < 4; ni++) {
        const int col = bn + wn + ni * 8 + tg * 2;
        const float bx = bias[col], by = bias[col + 1];
#pragma unroll
        for (int mi = 0; mi < 4; mi++) {
            const int row = bm + wm + mi * 16 + g;
            float2 w0, w1;
            w0.x = acc[mi][ni][0] + bx;
            w0.y = acc[mi][ni][1] + by;
            w1.x = acc[mi][ni][2] + bx;
            w1.y = acc[mi][ni][3] + by;
            *(float2*)&C[(size_t)row * N + col]       = w0;
            *(float2*)&C[(size_t)(row + 8) * N + col] = w1;
        }
    }
}

// ---------------------------------------------------------------------------
// Tensor-core flash attention. CTA = (b,h) x 128 q-rows; 8 warps x 16 rows.
// bf16 2-term split everywhere (hh + hl + lh). P stays in registers.
// smem (bf16): Qh/Ql[128][72], Kh/Kl[128][72], VTh/VTl[64][136]
// ---------------------------------------------------------------------------
#define AQLD 72
#define AVLD 136
#define Q_ELE (128 * AQLD)
#define V_ELE (64 * AVLD)
#define ATT_SMEM ((4 * Q_ELE + 2 * V_ELE) * 2)   // 108544 bytes

__global__ __launch_bounds__(256) void attn_tc(
    const float* __restrict__ qkv,  // [M_TOK][3*QKV]
    float* __restrict__ out)        // [M_TOK][QKV]
{
    extern __shared__ __nv_bfloat16 sb[];
    __nv_bfloat16* Qh = sb;
    __nv_bfloat16* Ql = sb + Q_ELE;
    __nv_bfloat16* Kh = sb + 2 * Q_ELE;
    __nv_bfloat16* Kl = sb + 3 * Q_ELE;
    __nv_bfloat16* Vh = sb + 4 * Q_ELE;
    __nv_bfloat16* Vl = sb + 4 * Q_ELE + V_ELE;

    const int tid = threadIdx.x;
    const int wid = tid >> 5;
    const int lid = tid & 31;
    const int g   = lid >> 2;
    const int tg  = lid & 3;
    const int qt  = blockIdx.x;
    const int bhx = blockIdx.y;
    const int b   = bhx >> 4;
    const int h   = bhx & 15;
    const int q0  = qt * 128;
    const size_t tok_base = (size_t)b * S_;
    const int hcol = h * D_;
    const int wrow = wid * 16;

    // loader mapping for Q/K: row = tid/2, col half = (tid&1)*32
    const int lr = tid >> 1;
    const int lch = (tid & 1) * 32;

    // load Q tile, pre-scaled by SCALE, split hi/lo
    {
        const float* qp = qkv + (tok_base + q0 + lr) * (size_t)N_QKV + hcol + lch;
        const int base = lr * AQLD + lch;
#pragma unroll
        for (int j = 0; j < 8; j++) {
            float4 v = *(const float4*)(qp + j * 4);
            v.x *= SCALE; v.y *= SCALE; v.z *= SCALE; v.w *= SCALE;
            uint32_t lo0, lo1;
            uint32_t hi0 = splitp(v.x, v.y, lo0);
            uint32_t hi1 = splitp(v.z, v.w, lo1);
            *(uint32_t*)&Qh[base + j * 4]     = hi0;
            *(uint32_t*)&Qh[base + j * 4 + 2] = hi1;
            *(uint32_t*)&Ql[base + j * 4]     = lo0;
            *(uint32_t*)&Ql[base + j * 4 + 2] = lo1;
        }
    }

    float acc_o[8][4];
#pragma unroll
    for (int dt = 0; dt < 8; dt++)
#pragma unroll
        for (int r = 0; r < 4; r++) acc_o[dt][r] = 0.f;
    float m0 = -INFINITY, m1 = -INFINITY, l0 = 0.f, l1 = 0.f;

    // V loader mapping: rows 2*(tid>>2), 2*(tid>>2)+1 ; cols (tid&3) + 4*cc
    const int vrp = (tid >> 2) * 2;
    const int vcg = tid & 3;

    for (int kt = 0; kt < S_ / 128; kt++) {
        const size_t kv0 = tok_base + (size_t)kt * 128;
        __syncthreads();   // prior-tile MMAs done reading smem

        // load K tile [128][64] split
        {
            const float* kp = qkv + (kv0 + lr) * (size_t)N_QKV + QKV_ + hcol + lch;
            const int base = lr * AQLD + lch;
#pragma unroll
            for (int j = 0; j < 8; j++) {
                float4 v = *(const float4*)(kp + j * 4);
                uint32_t lo0, lo1;
                uint32_t hi0 = splitp(v.x, v.y, lo0);
                uint32_t hi1 = splitp(v.z, v.w, lo1);
                *(uint32_t*)&Kh[base + j * 4]     = hi0;
                *(uint32_t*)&Kh[base + j * 4 + 2] = hi1;
                *(uint32_t*)&Kl[base + j * 4]     = lo0;
                *(uint32_t*)&Kl[base + j * 4 + 2] = lo1;
            }
        }
        // load V transposed: VT[d][kv], kv pairs packed
        {
            const float* vp0 = qkv + (kv0 + vrp) * (size_t)N_QKV + 2 * QKV_ + hcol;
            const float* vp1 = vp0 + N_QKV;
#pragma unroll
            for (int cc = 0; cc < 16; cc++) {
                const int c = vcg + cc * 4;
                float x = vp0[c], y = vp1[c];
                uint32_t lo;
                uint32_t hi = splitp(x, y, lo);
                *(uint32_t*)&Vh[c * AVLD + vrp] = hi;
                *(uint32_t*)&Vl[c * AVLD + vrp] = lo;
            }
        }
        __syncthreads();

        // ---- scores: 16 rows x 128 cols per warp, 16 n-tiles ----
        float accs[16][4];
#pragma unroll
        for (int nt = 0; nt < 16; nt++)
#pragma unroll
            for (int r = 0; r < 4; r++) accs[nt][r] = 0.f;

#pragma unroll
        for (int ks = 0; ks < 4; ks++) {
            const int ca = ks * 16 + tg * 2;
            const int ra = wrow + g;
            uint32_t ah[4], al[4];
            ah[0] = *(const uint32_t*)&Qh[ra * AQLD + ca];
            ah[1] = *(const uint32_t*)&Qh[(ra + 8) * AQLD + ca];
            ah[2] = *(const uint32_t*)&Qh[ra * AQLD + ca + 8];
            ah[3] = *(const uint32_t*)&Qh[(ra + 8) * AQLD + ca + 8];
            al[0] = *(const uint32_t*)&Ql[ra * AQLD + ca];
            al[1] = *(const uint32_t*)&Ql[(ra + 8) * AQLD + ca];
            al[2] = *(const uint32_t*)&Ql[ra * AQLD + ca + 8];
            al[3] = *(const uint32_t*)&Ql[(ra + 8) * AQLD + ca + 8];
#pragma unroll
            for (int nt = 0; nt < 16; nt++) {
                const int rb = nt * 8 + g;
                uint32_t kbh[2], kbl[2];
                kbh[0] = *(const uint32_t*)&Kh[rb * AQLD + ca];
                kbh[1] = *(const uint32_t*)&Kh[rb * AQLD + ca + 8];
                kbl[0] = *(const uint32_t*)&Kl[rb * AQLD + ca];
                kbl[1] = *(const uint32_t*)&Kl[rb * AQLD + ca + 8];
                mma16816(accs[nt], ah, kbh);
                mma16816(accs[nt], ah, kbl);
                mma16816(accs[nt], al, kbh);
            }
        }

        // ---- online softmax (rows g and g+8 of this warp's 16) ----
        float nm0 = m0, nm1 = m1;
#pragma unroll
        for (int nt = 0; nt < 16; nt++) {
            nm0 = fmaxf(nm0, fmaxf(accs[nt][0], accs[nt][1]));
            nm1 = fmaxf(nm1, fmaxf(accs[nt][2], accs[nt][3]));
        }
        nm0 = fmaxf(nm0, __shfl_xor_sync(0xffffffffu, nm0, 1));
        nm0 = fmaxf(nm0, __shfl_xor_sync(0xffffffffu, nm0, 2));
        nm1 = fmaxf(nm1, __shfl_xor_sync(0xffffffffu, nm1, 1));
        nm1 = fmaxf(nm1, __shfl_xor_sync(0xffffffffu, nm1, 2));
        const float corr0 = __expf(m0 - nm0);
        const float corr1 = __expf(m1 - nm1);
        float rs0 = 0.f, rs1 = 0.f;
#pragma unroll
        for (int nt = 0; nt < 16; nt++) {
            accs[nt][0] = __expf(accs[nt][0] - nm0);
            accs[nt][1] = __expf(accs[nt][1] - nm0);
            accs[nt][2] = __expf(accs[nt][2] - nm1);
            accs[nt][3] = __expf(accs[nt][3] - nm1);
            rs0 += accs[nt][0] + accs[nt][1];
            rs1 += accs[nt][2] + accs[nt][3];
        }
        rs0 += __shfl_xor_sync(0xffffffffu, rs0, 1);
        rs0 += __shfl_xor_sync(0xffffffffu, rs0, 2);
        rs1 += __shfl_xor_sync(0xffffffffu, rs1, 1);
        rs1 += __shfl_xor_sync(0xffffffffu, rs1, 2);
        l0 = l0 * corr0 + rs0;
        l1 = l1 * corr1 + rs1;
        m0 = nm0; m1 = nm1;
#pragma unroll
        for (int dt = 0; dt < 8; dt++) {
            acc_o[dt][0] *= corr0;
            acc_o[dt][1] *= corr0;
            acc_o[dt][2] *= corr1;
            acc_o[dt][3] *= corr1;
        }

        // ---- PV: P fragments straight from registers ----
#pragma unroll
        for (int kc = 0; kc < 8; kc++) {
            uint32_t pah[4], pal[4];
            pah[0] = splitp(accs[2 * kc][0],     accs[2 * kc][1],     pal[0]);
            pah[1] = splitp(accs[2 * kc][2],     accs[2 * kc][3],     pal[1]);
            pah[2] = splitp(accs[2 * kc + 1][0], accs[2 * kc + 1][1], pal[2]);
            pah[3] = splitp(accs[2 * kc + 1][2], accs[2 * kc + 1][3], pal[3]);
#pragma unroll
            for (int dt = 0; dt < 8; dt++) {
                const int vr = dt * 8 + g;
                const int vc = kc * 16 + tg * 2;
                uint32_t vbh[2], vbl[2];
                vbh[0] = *(const uint32_t*)&Vh[vr * AVLD + vc];
                vbh[1] = *(const uint32_t*)&Vh[vr * AVLD + vc + 8];
                vbl[0] = *(const uint32_t*)&Vl[vr * AVLD + vc];
                vbl[1] = *(const uint32_t*)&Vl[vr * AVLD + vc + 8];
                mma16816(acc_o[dt], pah, vbh);
                mma16816(acc_o[dt], pah, vbl);
                mma16816(acc_o[dt], pal, vbh);
            }
        }
    }

    // ---- write normalized output ----
    const float inv0 = 1.f / l0;
    const float inv1 = 1.f / l1;
    const size_t row0 = tok_base + q0 + wrow + g;
    const size_t row1 = row0 + 8;
#pragma unroll
    for (int dt = 0; dt < 8; dt++) {
        const int col = hcol + dt * 8 + tg * 2;
        float2 w0, w1;
        w0.x = acc_o[dt][0] * inv0; w0.y = acc_o[dt][1] * inv0;
        w1.x = acc_o[dt][2] * inv1; w1.y = acc_o[dt][3] * inv1;
        *(float2*)&out[row0 * QKV_ + col] = w0;
        *(float2*)&out[row1 * QKV_ + col] = w1;
    }
}

// ---------------------------------------------------------------------------
extern "C" void kernel_launch(void* const* d_in, const int* in_sizes, int n_in,
                              void* d_out, int out_size)
{
    const float* x     = (const float*)d_in[0];
    const float* w_qkv = (const float*)d_in[1];
    const float* b_qkv = (const float*)d_in[2];
    const float* w_o   = (const float*)d_in[3];
    const float* b_o   = (const float*)d_in[4];
    float* out = (float*)d_out;

    float *p_qkv, *p_att;
    cudaGetSymbolAddress((void**)&p_qkv, g_qkv);
    cudaGetSymbolAddress((void**)&p_att, g_att);

    cudaFuncSetAttribute(gemm_tc, cudaFuncAttributeMaxDynamicSharedMemorySize,
                         GEMM_SMEM);
    cudaFuncSetAttribute(attn_tc, cudaFuncAttributeMaxDynamicSharedMemorySize,
                         ATT_SMEM);

    // 1) QKV projection: [4096,3072]
    {
        dim3 grid(N_QKV / 128, M_TOK / 128);
        gemm_tc<<<grid, 256, GEMM_SMEM>>>(x, w_qkv, b_qkv, p_qkv, M_TOK, N_QKV, HID);
    }
    // 2) attention
    {
        dim3 grid(S_ / 128, B_ * H_);
        attn_tc<<<grid, 256, ATT_SMEM>>>(p_qkv, p_att);
    }
    // 3) output projection: [4096,1024]
    {
        dim3 grid(QKV_ / 128, M_TOK / 128);
        gemm_tc<<<grid, 256, GEMM_SMEM>>>(p_att, w_o, b_o, out, M_TOK, QKV_, HID);
    }
}

// round 7
// speedup vs baseline: 2.3359x; 1.2644x over previous
#include <cuda_runtime.h>
#include <cuda_bf16.h>
#include <math.h>
#include <stdint.h>

// Problem constants (fixed shapes)
#define B_    2
#define S_    2048
#define H_    16
#define D_    64
#define HID   1024
#define QKV_  1024
#define M_TOK 4096
#define N_QKV 3072
#define SCALE 0.125f

typedef unsigned long long u64;
typedef __nv_bfloat16 bf16;

// ---------------- helpers ----------------------------------------------------
__device__ __forceinline__ uint32_t pkbf(bf16 x, bf16 y) {
    __nv_bfloat162 t; t.x = x; t.y = y;
    return *(uint32_t*)&t;
}
__device__ __forceinline__ uint32_t splitp(float x, float y, uint32_t& lo) {
    bf16 hx = __float2bfloat16(x), hy = __float2bfloat16(y);
    bf16 lx = __float2bfloat16(x - __bfloat162float(hx));
    bf16 ly = __float2bfloat16(y - __bfloat162float(hy));
    lo = pkbf(lx, ly);
    return pkbf(hx, hy);
}
__device__ __forceinline__ void mma16816(float* d, const uint32_t* a, const uint32_t* b) {
    asm volatile(
        "mma.sync.aligned.m16n8k16.row.col.f32.bf16.bf16.f32 "
        "{%0,%1,%2,%3},{%4,%5,%6,%7},{%8,%9},{%0,%1,%2,%3};"
        : "+f"(d[0]), "+f"(d[1]), "+f"(d[2]), "+f"(d[3])
        : "r"(a[0]), "r"(a[1]), "r"(a[2]), "r"(a[3]), "r"(b[0]), "r"(b[1]));
}
__device__ __forceinline__ uint32_t smem_u32(const void* p) {
    uint32_t a;
    asm("{ .reg .u64 t; cvta.to.shared.u64 t, %1; cvt.u32.u64 %0, t; }" : "=r"(a) : "l"(p));
    return a;
}
__device__ __forceinline__ void cpa16(uint32_t d, const void* s) {
    asm volatile("cp.async.cg.shared.global [%0], [%1], 16;" :: "r"(d), "l"(s) : "memory");
}
#define CP_COMMIT() asm volatile("cp.async.commit_group;" ::: "memory")
#define CP_WAIT0()  asm volatile("cp.async.wait_group 0;" ::: "memory")
#define CP_WAIT1()  asm volatile("cp.async.wait_group 1;" ::: "memory")

// ---------------- scratch (device globals — no allocation) ------------------
__device__ float g_qkv[(size_t)M_TOK * N_QKV];
__device__ float g_att[(size_t)M_TOK * QKV_];
__device__ bf16 g_xh[(size_t)M_TOK * HID],   g_xl[(size_t)M_TOK * HID];
__device__ bf16 g_wqh[(size_t)N_QKV * HID],  g_wql[(size_t)N_QKV * HID];
__device__ bf16 g_woh[(size_t)HID * QKV_],   g_wol[(size_t)HID * QKV_];
__device__ bf16 g_ath[(size_t)M_TOK * QKV_], g_atl[(size_t)M_TOK * QKV_];
__device__ bf16 g_kh[(size_t)M_TOK * QKV_],  g_kl[(size_t)M_TOK * QKV_];
__device__ bf16 g_vh[(size_t)B_ * H_ * D_ * S_], g_vl[(size_t)B_ * H_ * D_ * S_];

// ---------------------------------------------------------------------------
// split kernels (memory-bound pre-passes)
// ---------------------------------------------------------------------------
__global__ __launch_bounds__(256) void split_plain(
    const float* __restrict__ src, int srcld, int c0, int C,
    bf16* __restrict__ h, bf16* __restrict__ l)
{
    const int e = (blockIdx.x * 256 + threadIdx.x) * 8;
    const int r = e / C, c = e % C;
    const float* p = src + (size_t)r * srcld + c0 + c;
    float4 a = *(const float4*)p;
    float4 b = *(const float4*)(p + 4);
    uint32_t l0, l1, l2, l3;
    uint32_t h0 = splitp(a.x, a.y, l0);
    uint32_t h1 = splitp(a.z, a.w, l1);
    uint32_t h2 = splitp(b.x, b.y, l2);
    uint32_t h3 = splitp(b.z, b.w, l3);
    *(uint4*)(h + (size_t)r * C + c) = make_uint4(h0, h1, h2, h3);
    *(uint4*)(l + (size_t)r * C + c) = make_uint4(l0, l1, l2, l3);
}

// transpose+split V: g_qkv[token][2048+h*64+d] -> g_v{h,l}[(bh*64+d)*2048 + s]
__global__ __launch_bounds__(256) void split_vt(
    const float* __restrict__ qkv, bf16* __restrict__ vh, bf16* __restrict__ vl)
{
    __shared__ float T[64][65];
    const int st = blockIdx.x;     // s-tile 0..31
    const int bh = blockIdx.y;     // 0..31
    const int b = bh >> 4, h = bh & 15;
    const int s0 = st * 64;
    const int tid = threadIdx.x;
    {
        const int sl = tid >> 2;
        const int cq = tid & 3;
        const float* src = qkv + ((size_t)(b * S_ + s0 + sl)) * N_QKV
                         + 2 * QKV_ + h * D_ + cq * 16;
#pragma unroll
        for (int j = 0; j < 4; j++) {
            float4 v = *(const float4*)(src + j * 4);
            T[cq * 16 + j * 4 + 0][sl] = v.x;
            T[cq * 16 + j * 4 + 1][sl] = v.y;
            T[cq * 16 + j * 4 + 2][sl] = v.z;
            T[cq * 16 + j * 4 + 3][sl] = v.w;
        }
    }
    __syncthreads();
    const int d = tid >> 2;
    const int sq = tid & 3;
    uint32_t hh[8], ll[8];
#pragma unroll
    for (int k = 0; k < 8; k++)
        hh[k] = splitp(T[d][sq * 16 + 2 * k], T[d][sq * 16 + 2 * k + 1], ll[k]);
    const size_t dst = (size_t)(bh * 64 + d) * S_ + s0 + sq * 16;
    *(uint4*)(vh + dst)     = make_uint4(hh[0], hh[1], hh[2], hh[3]);
    *(uint4*)(vh + dst + 8) = make_uint4(hh[4], hh[5], hh[6], hh[7]);
    *(uint4*)(vl + dst)     = make_uint4(ll[0], ll[1], ll[2], ll[3]);
    *(uint4*)(vl + dst + 8) = make_uint4(ll[4], ll[5], ll[6], ll[7]);
}

// ---------------------------------------------------------------------------
// Tensor-core NT GEMM v4 (bf16 pre-split operands, cp.async, 2 CTA/SM):
// C[M][N] = Ah*Bh^T + Ah*Bl^T + Al*Bh^T + bias
// CTA 128x128, BK=32, 8 warps (warp tile 64x32), 2-stage cp.async pipeline.
// ---------------------------------------------------------------------------
#define GLD2 40
#define GT_B (128 * GLD2 * 2)    // 10240 bytes per tile
#define GST_B (4 * GT_B)         // 40960 per stage (AH AL BH BL)
#define GEMM_SMEM (2 * GST_B)    // 81920

__global__ __launch_bounds__(256, 2) void gemm_bf(
    const bf16* __restrict__ Ah, const bf16* __restrict__ Al,
    const bf16* __restrict__ Bh, const bf16* __restrict__ Bl,
    const float* __restrict__ bias, float* __restrict__ C,
    int M, int N, int K)
{
    extern __shared__ char smem[];
    const uint32_t sb = smem_u32(smem);

    const int tid = threadIdx.x;
    const int wid = tid >> 5;
    const int lid = tid & 31;
    const int g   = lid >> 2;
    const int tg  = lid & 3;
    const int wm  = (wid & 1) * 64;
    const int wn  = (wid >> 1) * 32;
    const int bm  = blockIdx.y * 128;
    const int bn  = blockIdx.x * 128;

    const int lrow = tid >> 1;
    const int lq   = (tid & 1) * 2;   // 16B-unit pair index

    const bf16* pAh = Ah + (size_t)(bm + lrow) * K + lq * 8;
    const bf16* pAl = Al + (size_t)(bm + lrow) * K + lq * 8;
    const bf16* pBh = Bh + (size_t)(bn + lrow) * K + lq * 8;
    const bf16* pBl = Bl + (size_t)(bn + lrow) * K + lq * 8;
    const uint32_t dbase = sb + lrow * 80 + lq * 16;

    float acc[4][4][4];
#pragma unroll
    for (int mi = 0; mi < 4; mi++)
#pragma unroll
        for (int ni = 0; ni < 4; ni++)
#pragma unroll
            for (int r = 0; r < 4; r++) acc[mi][ni][r] = 0.f;

    const int nch = K / 32;

    auto issue = [&](int buf, int c) {
        const int k0 = c * 32;
        const uint32_t d = dbase + buf * GST_B;
        cpa16(d,                 pAh + k0);
        cpa16(d + 16,            pAh + k0 + 8);
        cpa16(d + GT_B,          pAl + k0);
        cpa16(d + GT_B + 16,     pAl + k0 + 8);
        cpa16(d + 2 * GT_B,      pBh + k0);
        cpa16(d + 2 * GT_B + 16, pBh + k0 + 8);
        cpa16(d + 3 * GT_B,      pBl + k0);
        cpa16(d + 3 * GT_B + 16, pBl + k0 + 8);
    };

    issue(0, 0);
    CP_COMMIT();

    for (int c = 0; c < nch; c++) {
        const int buf = c & 1;
        if (c + 1 < nch) {
            issue(buf ^ 1, c + 1);
            CP_COMMIT();
            CP_WAIT1();
        } else {
            CP_WAIT0();
        }
        __syncthreads();

        const bf16* AH = (const bf16*)(smem + buf * GST_B);
        const bf16* AL = (const bf16*)(smem + buf * GST_B + GT_B);
        const bf16* BH = (const bf16*)(smem + buf * GST_B + 2 * GT_B);
        const bf16* BL = (const bf16*)(smem + buf * GST_B + 3 * GT_B);

#pragma unroll
        for (int k2 = 0; k2 < 2; k2++) {
            const int kb = k2 * 16 + tg * 2;
            uint32_t bhf[4][2], blf[4][2];
#pragma unroll
            for (int ni = 0; ni < 4; ni++) {
                const int n = wn + ni * 8 + g;
                bhf[ni][0] = *(const uint32_t*)&BH[n * GLD2 + kb];
                bhf[ni][1] = *(const uint32_t*)&BH[n * GLD2 + kb + 8];
                blf[ni][0] = *(const uint32_t*)&BL[n * GLD2 + kb];
                blf[ni][1] = *(const uint32_t*)&BL[n * GLD2 + kb + 8];
            }
#pragma unroll
            for (int mi = 0; mi < 4; mi++) {
                const int r0 = wm + mi * 16 + g;
                uint32_t ah[4], al[4];
                ah[0] = *(const uint32_t*)&AH[r0 * GLD2 + kb];
                ah[1] = *(const uint32_t*)&AH[(r0 + 8) * GLD2 + kb];
                ah[2] = *(const uint32_t*)&AH[r0 * GLD2 + kb + 8];
                ah[3] = *(const uint32_t*)&AH[(r0 + 8) * GLD2 + kb + 8];
                al[0] = *(const uint32_t*)&AL[r0 * GLD2 + kb];
                al[1] = *(const uint32_t*)&AL[(r0 + 8) * GLD2 + kb];
                al[2] = *(const uint32_t*)&AL[r0 * GLD2 + kb + 8];
                al[3] = *(const uint32_t*)&AL[(r0 + 8) * GLD2 + kb + 8];
#pragma unroll
                for (int ni = 0; ni < 4; ni++) {
                    mma16816(acc[mi][ni], ah, bhf[ni]);
                    mma16816(acc[mi][ni], ah, blf[ni]);
                    mma16816(acc[mi][ni], al, bhf[ni]);
                }
            }
        }
        __syncthreads();
    }

#pragma unroll
    for (int ni = 0; ni < 4; ni++) {
        const int col = bn + wn + ni * 8 + tg * 2;
        const float bx = bias[col], by = bias[col + 1];
#pragma unroll
        for (int mi = 0; mi < 4; mi++) {
            const int row = bm + wm + mi * 16 + g;
            float2 w0, w1;
            w0.x = acc[mi][ni][0] + bx;
            w0.y = acc[mi][ni][1] + by;
            w1.x = acc[mi][ni][2] + bx;
            w1.y = acc[mi][ni][3] + by;
            *(float2*)&C[(size_t)row * N + col]       = w0;
            *(float2*)&C[(size_t)(row + 8) * N + col] = w1;
        }
    }
}

// ---------------------------------------------------------------------------
// Tensor-core flash attention v4: pre-split K/VT via cp.async double-buffer.
// CTA = (b,h) x 128 q-rows; 8 warps x 16 rows. P stays in registers.
// ---------------------------------------------------------------------------
#define AQLD 72
#define AVLD 136
#define QT_B (128 * AQLD * 2)    // 18432
#define VT_B (64 * AVLD * 2)     // 17408
#define OFF_QH 0
#define OFF_QL QT_B
#define OFF_K0 (2 * QT_B)                       // KH,KL buf0
#define OFF_V0 (2 * QT_B + 4 * QT_B)            // after 2 K bufs (each 2*QT_B)
#define ATT_SMEM (2 * QT_B + 4 * QT_B + 4 * VT_B)   // 180224

__global__ __launch_bounds__(256) void attn_tc(
    const float* __restrict__ qkv,
    const bf16* __restrict__ kh_g, const bf16* __restrict__ kl_g,
    const bf16* __restrict__ vh_g, const bf16* __restrict__ vl_g,
    float* __restrict__ out)
{
    extern __shared__ char smc[];
    const uint32_t sb = smem_u32(smc);
    bf16* Qh = (bf16*)(smc + OFF_QH);
    bf16* Ql = (bf16*)(smc + OFF_QL);

    const int tid = threadIdx.x;
    const int wid = tid >> 5;
    const int lid = tid & 31;
    const int g   = lid >> 2;
    const int tg  = lid & 3;
    const int qt  = blockIdx.x;
    const int bhx = blockIdx.y;
    const int b   = bhx >> 4;
    const int h   = bhx & 15;
    const int q0  = qt * 128;
    const size_t tok_base = (size_t)b * S_;
    const int hcol = h * D_;
    const int wrow = wid * 16;

    // Q load: fp32 -> scaled hi/lo bf16
    {
        const int lr  = tid >> 1;
        const int lch = (tid & 1) * 32;
        const float* qp = qkv + (tok_base + q0 + lr) * (size_t)N_QKV + hcol + lch;
        const int base = lr * AQLD + lch;
#pragma unroll
        for (int j = 0; j < 8; j++) {
            float4 v = *(const float4*)(qp + j * 4);
            v.x *= SCALE; v.y *= SCALE; v.z *= SCALE; v.w *= SCALE;
            uint32_t lo0, lo1;
            uint32_t hi0 = splitp(v.x, v.y, lo0);
            uint32_t hi1 = splitp(v.z, v.w, lo1);
            *(uint32_t*)&Qh[base + j * 4]     = hi0;
            *(uint32_t*)&Qh[base + j * 4 + 2] = hi1;
            *(uint32_t*)&Ql[base + j * 4]     = lo0;
            *(uint32_t*)&Ql[base + j * 4 + 2] = lo1;
        }
    }

    // K/V loaders
    const int krow = tid >> 1;
    const int kq   = (tid & 1) * 4;
    const int vd   = tid >> 2;
    const int vq   = (tid & 3) * 4;
    const bf16* pkh = kh_g + (tok_base + krow) * (size_t)QKV_ + hcol + kq * 8;
    const bf16* pkl = kl_g + (tok_base + krow) * (size_t)QKV_ + hcol + kq * 8;
    const bf16* pvh = vh_g + (size_t)(bhx * 64 + vd) * S_ + vq * 8;
    const bf16* pvl = vl_g + (size_t)(bhx * 64 + vd) * S_ + vq * 8;
    const uint32_t dk = sb + OFF_K0 + krow * 144 + kq * 16;
    const uint32_t dv = sb + OFF_V0 + vd * 272 + vq * 16;

    auto issue_kv = [&](int buf, int kt) {
        const int kv0 = kt * 128;
        const uint32_t dkb = dk + buf * (2 * QT_B);
        const uint32_t dvb = dv + buf * (2 * VT_B);
        const size_t koff = (size_t)kv0 * QKV_;
#pragma unroll
        for (int i = 0; i < 4; i++) {
            cpa16(dkb + i * 16,        pkh + koff + i * 8);
            cpa16(dkb + QT_B + i * 16, pkl + koff + i * 8);
            cpa16(dvb + i * 16,        pvh + kv0 + i * 8);
            cpa16(dvb + VT_B + i * 16, pvl + kv0 + i * 8);
        }
    };

    float acc_o[8][4];
#pragma unroll
    for (int dt = 0; dt < 8; dt++)
#pragma unroll
        for (int r = 0; r < 4; r++) acc_o[dt][r] = 0.f;
    float m0 = -INFINITY, m1 = -INFINITY, l0 = 0.f, l1 = 0.f;

    issue_kv(0, 0);
    CP_COMMIT();

    for (int kt = 0; kt < S_ / 128; kt++) {
        const int buf = kt & 1;
        if (kt + 1 < S_ / 128) {
            issue_kv(buf ^ 1, kt + 1);
            CP_COMMIT();
            CP_WAIT1();
        } else {
            CP_WAIT0();
        }
        __syncthreads();

        const bf16* Kh = (const bf16*)(smc + OFF_K0 + buf * (2 * QT_B));
        const bf16* Kl = (const bf16*)(smc + OFF_K0 + buf * (2 * QT_B) + QT_B);
        const bf16* Vh = (const bf16*)(smc + OFF_V0 + buf * (2 * VT_B));
        const bf16* Vl = (const bf16*)(smc + OFF_V0 + buf * (2 * VT_B) + VT_B);

        // ---- scores ----
        float accs[16][4];
#pragma unroll
        for (int nt = 0; nt < 16; nt++)
#pragma unroll
            for (int r = 0; r < 4; r++) accs[nt][r] = 0.f;

#pragma unroll
        for (int ks = 0; ks < 4; ks++) {
            const int ca = ks * 16 + tg * 2;
            const int ra = wrow + g;
            uint32_t ah[4], al[4];
            ah[0] = *(const uint32_t*)&Qh[ra * AQLD + ca];
            ah[1] = *(const uint32_t*)&Qh[(ra + 8) * AQLD + ca];
            ah[2] = *(const uint32_t*)&Qh[ra * AQLD + ca + 8];
            ah[3] = *(const uint32_t*)&Qh[(ra + 8) * AQLD + ca + 8];
            al[0] = *(const uint32_t*)&Ql[ra * AQLD + ca];
            al[1] = *(const uint32_t*)&Ql[(ra + 8) * AQLD + ca];
            al[2] = *(const uint32_t*)&Ql[ra * AQLD + ca + 8];
            al[3] = *(const uint32_t*)&Ql[(ra + 8) * AQLD + ca + 8];
#pragma unroll
            for (int nt = 0; nt < 16; nt++) {
                const int rb = nt * 8 + g;
                uint32_t kbh[2], kbl[2];
                kbh[0] = *(const uint32_t*)&Kh[rb * AQLD + ca];
                kbh[1] = *(const uint32_t*)&Kh[rb * AQLD + ca + 8];
                kbl[0] = *(const uint32_t*)&Kl[rb * AQLD + ca];
                kbl[1] = *(const uint32_t*)&Kl[rb * AQLD + ca + 8];
                mma16816(accs[nt], ah, kbh);
                mma16816(accs[nt], ah, kbl);
                mma16816(accs[nt], al, kbh);
            }
        }

        // ---- online softmax ----
        float nm0 = m0, nm1 = m1;
#pragma unroll
        for (int nt = 0; nt < 16; nt++) {
            nm0 = fmaxf(nm0, fmaxf(accs[nt][0], accs[nt][1]));
            nm1 = fmaxf(nm1, fmaxf(accs[nt][2], accs[nt][3]));
        }
        nm0 = fmaxf(nm0, __shfl_xor_sync(0xffffffffu, nm0, 1));
        nm0 = fmaxf(nm0, __shfl_xor_sync(0xffffffffu, nm0, 2));
        nm1 = fmaxf(nm1, __shfl_xor_sync(0xffffffffu, nm1, 1));
        nm1 = fmaxf(nm1, __shfl_xor_sync(0xffffffffu, nm1, 2));
        const float corr0 = __expf(m0 - nm0);
        const float corr1 = __expf(m1 - nm1);
        float rs0 = 0.f, rs1 = 0.f;
#pragma unroll
        for (int nt = 0; nt < 16; nt++) {
            accs[nt][0] = __expf(accs[nt][0] - nm0);
            accs[nt][1] = __expf(accs[nt][1] - nm0);
            accs[nt][2] = __expf(accs[nt][2] - nm1);
            accs[nt][3] = __expf(accs[nt][3] - nm1);
            rs0 += accs[nt][0] + accs[nt][1];
            rs1 += accs[nt][2] + accs[nt][3];
        }
        rs0 += __shfl_xor_sync(0xffffffffu, rs0, 1);
        rs0 += __shfl_xor_sync(0xffffffffu, rs0, 2);
        rs1 += __shfl_xor_sync(0xffffffffu, rs1, 1);
        rs1 += __shfl_xor_sync(0xffffffffu, rs1, 2);
        l0 = l0 * corr0 + rs0;
        l1 = l1 * corr1 + rs1;
        m0 = nm0; m1 = nm1;
#pragma unroll
        for (int dt = 0; dt < 8; dt++) {
            acc_o[dt][0] *= corr0;
            acc_o[dt][1] *= corr0;
            acc_o[dt][2] *= corr1;
            acc_o[dt][3] *= corr1;
        }

        // ---- PV ----
#pragma unroll
        for (int kc = 0; kc < 8; kc++) {
            uint32_t pah[4], pal[4];
            pah[0] = splitp(accs[2 * kc][0],     accs[2 * kc][1],     pal[0]);
            pah[1] = splitp(accs[2 * kc][2],     accs[2 * kc][3],     pal[1]);
            pah[2] = splitp(accs[2 * kc + 1][0], accs[2 * kc + 1][1], pal[2]);
            pah[3] = splitp(accs[2 * kc + 1][2], accs[2 * kc + 1][3], pal[3]);
#pragma unroll
            for (int dt = 0; dt < 8; dt++) {
                const int vr = dt * 8 + g;
                const int vc = kc * 16 + tg * 2;
                uint32_t vbh[2], vbl[2];
                vbh[0] = *(const uint32_t*)&Vh[vr * AVLD + vc];
                vbh[1] = *(const uint32_t*)&Vh[vr * AVLD + vc + 8];
                vbl[0] = *(const uint32_t*)&Vl[vr * AVLD + vc];
                vbl[1] = *(const uint32_t*)&Vl[vr * AVLD + vc + 8];
                mma16816(acc_o[dt], pah, vbh);
                mma16816(acc_o[dt], pah, vbl);
                mma16816(acc_o[dt], pal, vbh);
            }
        }
        __syncthreads();
    }

    // ---- write normalized output ----
    const float inv0 = 1.f / l0;
    const float inv1 = 1.f / l1;
    const size_t row0 = tok_base + q0 + wrow + g;
    const size_t row1 = row0 + 8;
#pragma unroll
    for (int dt = 0; dt < 8; dt++) {
        const int col = hcol + dt * 8 + tg * 2;
        float2 w0, w1;
        w0.x = acc_o[dt][0] * inv0; w0.y = acc_o[dt][1] * inv0;
        w1.x = acc_o[dt][2] * inv1; w1.y = acc_o[dt][3] * inv1;
        *(float2*)&out[row0 * QKV_ + col] = w0;
        *(float2*)&out[row1 * QKV_ + col] = w1;
    }
}

// ---------------------------------------------------------------------------
extern "C" void kernel_launch(void* const* d_in, const int* in_sizes, int n_in,
                              void* d_out, int out_size)
{
    const float* x     = (const float*)d_in[0];
    const float* w_qkv = (const float*)d_in[1];
    const float* b_qkv = (const float*)d_in[2];
    const float* w_o   = (const float*)d_in[3];
    const float* b_o   = (const float*)d_in[4];
    float* out = (float*)d_out;

    float *p_qkv, *p_att;
    bf16 *p_xh, *p_xl, *p_wqh, *p_wql, *p_woh, *p_wol;
    bf16 *p_ath, *p_atl, *p_kh, *p_kl, *p_vh, *p_vl;
    cudaGetSymbolAddress((void**)&p_qkv, g_qkv);
    cudaGetSymbolAddress((void**)&p_att, g_att);
    cudaGetSymbolAddress((void**)&p_xh, g_xh);
    cudaGetSymbolAddress((void**)&p_xl, g_xl);
    cudaGetSymbolAddress((void**)&p_wqh, g_wqh);
    cudaGetSymbolAddress((void**)&p_wql, g_wql);
    cudaGetSymbolAddress((void**)&p_woh, g_woh);
    cudaGetSymbolAddress((void**)&p_wol, g_wol);
    cudaGetSymbolAddress((void**)&p_ath, g_ath);
    cudaGetSymbolAddress((void**)&p_atl, g_atl);
    cudaGetSymbolAddress((void**)&p_kh, g_kh);
    cudaGetSymbolAddress((void**)&p_kl, g_kl);
    cudaGetSymbolAddress((void**)&p_vh, g_vh);
    cudaGetSymbolAddress((void**)&p_vl, g_vl);

    cudaFuncSetAttribute(gemm_bf, cudaFuncAttributeMaxDynamicSharedMemorySize,
                         GEMM_SMEM);
    cudaFuncSetAttribute(attn_tc, cudaFuncAttributeMaxDynamicSharedMemorySize,
                         ATT_SMEM);

    // pre-split inputs and weights
    split_plain<<<(M_TOK * HID) / 2048, 256>>>(x, HID, 0, HID, p_xh, p_xl);
    split_plain<<<(N_QKV * HID) / 2048, 256>>>(w_qkv, HID, 0, HID, p_wqh, p_wql);
    split_plain<<<(HID * QKV_) / 2048, 256>>>(w_o, QKV_, 0, QKV_, p_woh, p_wol);

    // 1) QKV projection
    {
        dim3 grid(N_QKV / 128, M_TOK / 128);
        gemm_bf<<<grid, 256, GEMM_SMEM>>>(p_xh, p_xl, p_wqh, p_wql, b_qkv, p_qkv,
                                          M_TOK, N_QKV, HID);
    }

    // split K (middle 1024 cols) and transposed V
    split_plain<<<(M_TOK * QKV_) / 2048, 256>>>(p_qkv, N_QKV, QKV_, QKV_, p_kh, p_kl);
    {
        dim3 grid(S_ / 64, B_ * H_);
        split_vt<<<grid, 256>>>(p_qkv, p_vh, p_vl);
    }

    // 2) attention
    {
        dim3 grid(S_ / 128, B_ * H_);
        attn_tc<<<grid, 256, ATT_SMEM>>>(p_qkv, p_kh, p_kl, p_vh, p_vl, p_att);
    }

    // split attention output, then 3) output projection
    split_plain<<<(M_TOK * QKV_) / 2048, 256>>>(p_att, QKV_, 0, QKV_, p_ath, p_atl);
    {
        dim3 grid(QKV_ / 128, M_TOK / 128);
        gemm_bf<<<grid, 256, GEMM_SMEM>>>(p_ath, p_atl, p_woh, p_wol, b_o, out,
                                          M_TOK, QKV_, HID);
    }
}

// round 8
// speedup vs baseline: 2.4059x; 1.0300x over previous
#include <cuda_runtime.h>
#include <cuda_bf16.h>
#include <math.h>
#include <stdint.h>

#define B_    2
#define S_    2048
#define H_    16
#define D_    64
#define HID   1024
#define QKV_  1024
#define M_TOK 4096
#define N_QKV 3072
#define SCALE 0.125f

typedef unsigned long long u64;
typedef __nv_bfloat16 bf16;

// ---------------- helpers ----------------------------------------------------
__device__ __forceinline__ uint32_t pkbf(bf16 x, bf16 y) {
    __nv_bfloat162 t; t.x = x; t.y = y;
    return *(uint32_t*)&t;
}
__device__ __forceinline__ uint32_t splitp(float x, float y, uint32_t& lo) {
    bf16 hx = __float2bfloat16(x), hy = __float2bfloat16(y);
    bf16 lx = __float2bfloat16(x - __bfloat162float(hx));
    bf16 ly = __float2bfloat16(y - __bfloat162float(hy));
    lo = pkbf(lx, ly);
    return pkbf(hx, hy);
}
__device__ __forceinline__ void mma16816(float* d,
    uint32_t a0, uint32_t a1, uint32_t a2, uint32_t a3, uint32_t b0, uint32_t b1) {
    asm volatile(
        "mma.sync.aligned.m16n8k16.row.col.f32.bf16.bf16.f32 "
        "{%0,%1,%2,%3},{%4,%5,%6,%7},{%8,%9},{%0,%1,%2,%3};"
        : "+f"(d[0]), "+f"(d[1]), "+f"(d[2]), "+f"(d[3])
        : "r"(a0), "r"(a1), "r"(a2), "r"(a3), "r"(b0), "r"(b1));
}
__device__ __forceinline__ void ldsm4(uint32_t* r, uint32_t addr) {
    asm volatile("ldmatrix.sync.aligned.m8n8.x4.shared.b16 {%0,%1,%2,%3},[%4];"
                 : "=r"(r[0]), "=r"(r[1]), "=r"(r[2]), "=r"(r[3]) : "r"(addr));
}
__device__ __forceinline__ uint32_t smem_u32(const void* p) {
    uint32_t a;
    asm("{ .reg .u64 t; cvta.to.shared.u64 t, %1; cvt.u32.u64 %0, t; }" : "=r"(a) : "l"(p));
    return a;
}
__device__ __forceinline__ void cpa16(uint32_t d, const void* s) {
    asm volatile("cp.async.cg.shared.global [%0], [%1], 16;" :: "r"(d), "l"(s) : "memory");
}
#define CP_COMMIT() asm volatile("cp.async.commit_group;" ::: "memory")
#define CP_WAIT0()  asm volatile("cp.async.wait_group 0;" ::: "memory")
#define CP_WAIT1()  asm volatile("cp.async.wait_group 1;" ::: "memory")

// ---------------- scratch ----------------------------------------------------
__device__ float g_qkv[(size_t)M_TOK * N_QKV];
__device__ bf16 g_xh[(size_t)M_TOK * HID],   g_xl[(size_t)M_TOK * HID];
__device__ bf16 g_wqh[(size_t)N_QKV * HID],  g_wql[(size_t)N_QKV * HID];
__device__ bf16 g_woh[(size_t)HID * QKV_],   g_wol[(size_t)HID * QKV_];
__device__ bf16 g_ath[(size_t)M_TOK * QKV_], g_atl[(size_t)M_TOK * QKV_];
__device__ bf16 g_kh[(size_t)M_TOK * QKV_],  g_kl[(size_t)M_TOK * QKV_];
__device__ bf16 g_vh[(size_t)B_ * H_ * D_ * S_], g_vl[(size_t)B_ * H_ * D_ * S_];

// ---------------------------------------------------------------------------
// split pre-passes
// ---------------------------------------------------------------------------
__global__ __launch_bounds__(256) void split_plain(
    const float* __restrict__ src, bf16* __restrict__ h, bf16* __restrict__ l)
{
    const size_t e = ((size_t)blockIdx.x * 256 + threadIdx.x) * 8;
    float4 a = *(const float4*)(src + e);
    float4 b = *(const float4*)(src + e + 4);
    uint32_t l0, l1, l2, l3;
    uint32_t h0 = splitp(a.x, a.y, l0);
    uint32_t h1 = splitp(a.z, a.w, l1);
    uint32_t h2 = splitp(b.x, b.y, l2);
    uint32_t h3 = splitp(b.z, b.w, l3);
    *(uint4*)(h + e) = make_uint4(h0, h1, h2, h3);
    *(uint4*)(l + e) = make_uint4(l0, l1, l2, l3);
}

__global__ __launch_bounds__(256) void split_vt(
    const float* __restrict__ qkv, bf16* __restrict__ vh, bf16* __restrict__ vl)
{
    __shared__ float T[64][65];
    const int st = blockIdx.x;
    const int bh = blockIdx.y;
    const int b = bh >> 4, h = bh & 15;
    const int s0 = st * 64;
    const int tid = threadIdx.x;
    {
        const int sl = tid >> 2;
        const int cq = tid & 3;
        const float* src = qkv + ((size_t)(b * S_ + s0 + sl)) * N_QKV
                         + 2 * QKV_ + h * D_ + cq * 16;
#pragma unroll
        for (int j = 0; j < 4; j++) {
            float4 v = *(const float4*)(src + j * 4);
            T[cq * 16 + j * 4 + 0][sl] = v.x;
            T[cq * 16 + j * 4 + 1][sl] = v.y;
            T[cq * 16 + j * 4 + 2][sl] = v.z;
            T[cq * 16 + j * 4 + 3][sl] = v.w;
        }
    }
    __syncthreads();
    const int d = tid >> 2;
    const int sq = tid & 3;
    uint32_t hh[8], ll[8];
#pragma unroll
    for (int k = 0; k < 8; k++)
        hh[k] = splitp(T[d][sq * 16 + 2 * k], T[d][sq * 16 + 2 * k + 1], ll[k]);
    const size_t dst = (size_t)(bh * 64 + d) * S_ + s0 + sq * 16;
    *(uint4*)(vh + dst)     = make_uint4(hh[0], hh[1], hh[2], hh[3]);
    *(uint4*)(vh + dst + 8) = make_uint4(hh[4], hh[5], hh[6], hh[7]);
    *(uint4*)(vl + dst)     = make_uint4(ll[0], ll[1], ll[2], ll[3]);
    *(uint4*)(vl + dst + 8) = make_uint4(ll[4], ll[5], ll[6], ll[7]);
}

// ---------------------------------------------------------------------------
// Tensor-core NT GEMM (ldmatrix + single-sync multistage, 2 CTA/SM)
// C = Ah*Bh^T + Ah*Bl^T + Al*Bh^T + bias ;  optional bf16-split K-column output
// ---------------------------------------------------------------------------
#define GLD2 40
#define GT_B (128 * GLD2 * 2)
#define GST_B (4 * GT_B)
#define GEMM_SMEM (2 * GST_B)

__global__ __launch_bounds__(256, 2) void gemm_bf(
    const bf16* __restrict__ Ah, const bf16* __restrict__ Al,
    const bf16* __restrict__ Bh, const bf16* __restrict__ Bl,
    const float* __restrict__ bias, float* __restrict__ C,
    bf16* __restrict__ kh, bf16* __restrict__ kl,
    int M, int N, int K, int kmode)
{
    extern __shared__ char smem[];
    const uint32_t sb = smem_u32(smem);

    const int tid = threadIdx.x;
    const int wid = tid >> 5;
    const int lid = tid & 31;
    const int g   = lid >> 2;
    const int tg  = lid & 3;
    const int wm  = (wid & 1) * 64;
    const int wn  = (wid >> 1) * 32;
    const int bm  = blockIdx.y * 128;
    const int bn  = blockIdx.x * 128;

    const int lrow = tid >> 1;
    const int lq   = (tid & 1) * 2;

    const bf16* pAh = Ah + (size_t)(bm + lrow) * K + lq * 8;
    const bf16* pAl = Al + (size_t)(bm + lrow) * K + lq * 8;
    const bf16* pBh = Bh + (size_t)(bn + lrow) * K + lq * 8;
    const bf16* pBl = Bl + (size_t)(bn + lrow) * K + lq * 8;
    const uint32_t dbase = sb + lrow * 80 + lq * 16;

    // LDSM per-lane address pieces
    const uint32_t aLane = (uint32_t)((lid & 15) * GLD2 + ((lid >> 4) << 3)) * 2;
    const uint32_t bLane = (uint32_t)((wn + lid) * GLD2) * 2;

    float acc[4][4][4];
#pragma unroll
    for (int mi = 0; mi < 4; mi++)
#pragma unroll
        for (int ni = 0; ni < 4; ni++)
#pragma unroll
            for (int r = 0; r < 4; r++) acc[mi][ni][r] = 0.f;

    const int nch = K / 32;

    auto issue = [&](int buf, int c) {
        const int k0 = c * 32;
        const uint32_t d = dbase + buf * GST_B;
        cpa16(d,                 pAh + k0);
        cpa16(d + 16,            pAh + k0 + 8);
        cpa16(d + GT_B,          pAl + k0);
        cpa16(d + GT_B + 16,     pAl + k0 + 8);
        cpa16(d + 2 * GT_B,      pBh + k0);
        cpa16(d + 2 * GT_B + 16, pBh + k0 + 8);
        cpa16(d + 3 * GT_B,      pBl + k0);
        cpa16(d + 3 * GT_B + 16, pBl + k0 + 8);
    };

    issue(0, 0);
    CP_COMMIT();

    for (int c = 0; c < nch; c++) {
        const int buf = c & 1;
        if (c + 1 < nch) {
            issue(buf ^ 1, c + 1);
            CP_COMMIT();
            CP_WAIT1();
        } else {
            CP_WAIT0();
        }
        __syncthreads();

        const uint32_t sAH = sb + buf * GST_B;
        const uint32_t sAL = sAH + GT_B;
        const uint32_t sBH = sAH + 2 * GT_B;
        const uint32_t sBL = sAH + 3 * GT_B;

#pragma unroll
        for (int k2 = 0; k2 < 2; k2++) {
            const uint32_t kOff = k2 * 32;
            uint32_t bh0[4], bh1[4], bl0[4], bl1[4];
            ldsm4(bh0, sBH + bLane + kOff);
            ldsm4(bh1, sBH + bLane + kOff + 16);
            ldsm4(bl0, sBL + bLane + kOff);
            ldsm4(bl1, sBL + bLane + kOff + 16);
#pragma unroll
            for (int mi = 0; mi < 4; mi++) {
                const uint32_t rOff = (uint32_t)(wm + mi * 16) * 80 + aLane + kOff;
                uint32_t ah[4], al[4];
                ldsm4(ah, sAH + rOff);
                ldsm4(al, sAL + rOff);
#pragma unroll
                for (int ni = 0; ni < 4; ni++)
                    mma16816(acc[mi][ni], ah[0], ah[1], ah[2], ah[3], bh0[ni], bh1[ni]);
#pragma unroll
                for (int ni = 0; ni < 4; ni++)
                    mma16816(acc[mi][ni], ah[0], ah[1], ah[2], ah[3], bl0[ni], bl1[ni]);
#pragma unroll
                for (int ni = 0; ni < 4; ni++)
                    mma16816(acc[mi][ni], al[0], al[1], al[2], al[3], bh0[ni], bh1[ni]);
            }
        }
        __syncthreads();
    }

    const bool ksplit = kmode && (bn >= QKV_) && (bn < 2 * QKV_);
    if (ksplit) {
#pragma unroll
        for (int ni = 0; ni < 4; ni++) {
            const int col = bn + wn + ni * 8 + tg * 2;
            const float bx = bias[col], by = bias[col + 1];
            const int kc = col - QKV_;
#pragma unroll
            for (int mi = 0; mi < 4; mi++) {
                const int row = bm + wm + mi * 16 + g;
                uint32_t lo0, lo1;
                uint32_t hi0 = splitp(acc[mi][ni][0] + bx, acc[mi][ni][1] + by, lo0);
                uint32_t hi1 = splitp(acc[mi][ni][2] + bx, acc[mi][ni][3] + by, lo1);
                *(uint32_t*)&kh[(size_t)row * QKV_ + kc]       = hi0;
                *(uint32_t*)&kl[(size_t)row * QKV_ + kc]       = lo0;
                *(uint32_t*)&kh[(size_t)(row + 8) * QKV_ + kc] = hi1;
                *(uint32_t*)&kl[(size_t)(row + 8) * QKV_ + kc] = lo1;
            }
        }
    } else {
#pragma unroll
        for (int ni = 0; ni < 4; ni++) {
            const int col = bn + wn + ni * 8 + tg * 2;
            const float bx = bias[col], by = bias[col + 1];
#pragma unroll
            for (int mi = 0; mi < 4; mi++) {
                const int row = bm + wm + mi * 16 + g;
                float2 w0, w1;
                w0.x = acc[mi][ni][0] + bx;
                w0.y = acc[mi][ni][1] + by;
                w1.x = acc[mi][ni][2] + bx;
                w1.y = acc[mi][ni][3] + by;
                *(float2*)&C[(size_t)row * N + col]       = w0;
                *(float2*)&C[(size_t)(row + 8) * N + col] = w1;
            }
        }
    }
}

// ---------------------------------------------------------------------------
// Tensor-core flash attention (ldmatrix, single-sync, split output epilogue)
// ---------------------------------------------------------------------------
#define AQLD 72
#define AVLD 136
#define QT_B (128 * AQLD * 2)
#define VT_B (64 * AVLD * 2)
#define OFF_QH 0
#define OFF_QL QT_B
#define OFF_K0 (2 * QT_B)
#define OFF_V0 (2 * QT_B + 4 * QT_B)
#define ATT_SMEM (2 * QT_B + 4 * QT_B + 4 * VT_B)

__global__ __launch_bounds__(256) void attn_tc(
    const float* __restrict__ qkv,
    const bf16* __restrict__ kh_g, const bf16* __restrict__ kl_g,
    const bf16* __restrict__ vh_g, const bf16* __restrict__ vl_g,
    bf16* __restrict__ oh, bf16* __restrict__ ol)
{
    extern __shared__ char smc[];
    const uint32_t sb = smem_u32(smc);
    bf16* Qh = (bf16*)(smc + OFF_QH);
    bf16* Ql = (bf16*)(smc + OFF_QL);

    const int tid = threadIdx.x;
    const int wid = tid >> 5;
    const int lid = tid & 31;
    const int g   = lid >> 2;
    const int tg  = lid & 3;
    const int qt  = blockIdx.x;
    const int bhx = blockIdx.y;
    const int b   = bhx >> 4;
    const int h   = bhx & 15;
    const int q0  = qt * 128;
    const size_t tok_base = (size_t)b * S_;
    const int hcol = h * D_;
    const int wrow = wid * 16;

    // Q load: fp32 -> scaled hi/lo bf16
    {
        const int lr  = tid >> 1;
        const int lch = (tid & 1) * 32;
        const float* qp = qkv + (tok_base + q0 + lr) * (size_t)N_QKV + hcol + lch;
        const int base = lr * AQLD + lch;
#pragma unroll
        for (int j = 0; j < 8; j++) {
            float4 v = *(const float4*)(qp + j * 4);
            v.x *= SCALE; v.y *= SCALE; v.z *= SCALE; v.w *= SCALE;
            uint32_t lo0, lo1;
            uint32_t hi0 = splitp(v.x, v.y, lo0);
            uint32_t hi1 = splitp(v.z, v.w, lo1);
            *(uint32_t*)&Qh[base + j * 4]     = hi0;
            *(uint32_t*)&Qh[base + j * 4 + 2] = hi1;
            *(uint32_t*)&Ql[base + j * 4]     = lo0;
            *(uint32_t*)&Ql[base + j * 4 + 2] = lo1;
        }
    }

    // cp.async loader mappings
    const int krow = tid >> 1;
    const int kq   = (tid & 1) * 4;
    const int vd   = tid >> 2;
    const int vq   = (tid & 3) * 4;
    const bf16* pkh = kh_g + (tok_base + krow) * (size_t)QKV_ + hcol + kq * 8;
    const bf16* pkl = kl_g + (tok_base + krow) * (size_t)QKV_ + hcol + kq * 8;
    const bf16* pvh = vh_g + (size_t)(bhx * 64 + vd) * S_ + vq * 8;
    const bf16* pvl = vl_g + (size_t)(bhx * 64 + vd) * S_ + vq * 8;
    const uint32_t dk = sb + OFF_K0 + krow * 144 + kq * 16;
    const uint32_t dv = sb + OFF_V0 + vd * 272 + vq * 16;

    auto issue_kv = [&](int buf, int kt) {
        const int kv0 = kt * 128;
        const uint32_t dkb = dk + buf * (2 * QT_B);
        const uint32_t dvb = dv + buf * (2 * VT_B);
        const size_t koff = (size_t)kv0 * QKV_;
#pragma unroll
        for (int i = 0; i < 4; i++) {
            cpa16(dkb + i * 16,        pkh + koff + i * 8);
            cpa16(dkb + QT_B + i * 16, pkl + koff + i * 8);
            cpa16(dvb + i * 16,        pvh + kv0 + i * 8);
            cpa16(dvb + VT_B + i * 16, pvl + kv0 + i * 8);
        }
    };

    // LDSM per-lane pieces
    const uint32_t qLane = (uint32_t)((wrow + (lid & 15)) * AQLD + ((lid >> 4) << 3)) * 2;
    const uint32_t kLane = (uint32_t)lid * 144;
    const uint32_t vLane = (uint32_t)lid * 272;

    float acc_o[8][4];
#pragma unroll
    for (int dt = 0; dt < 8; dt++)
#pragma unroll
        for (int r = 0; r < 4; r++) acc_o[dt][r] = 0.f;
    float m0 = -INFINITY, m1 = -INFINITY, l0 = 0.f, l1 = 0.f;

    issue_kv(0, 0);
    CP_COMMIT();

    for (int kt = 0; kt < S_ / 128; kt++) {
        const int buf = kt & 1;
        if (kt + 1 < S_ / 128) {
            issue_kv(buf ^ 1, kt + 1);
            CP_COMMIT();
            CP_WAIT1();
        } else {
            CP_WAIT0();
        }
        __syncthreads();

        const uint32_t sKH = sb + OFF_K0 + buf * (2 * QT_B);
        const uint32_t sKL = sKH + QT_B;
        const uint32_t sVH = sb + OFF_V0 + buf * (2 * VT_B);
        const uint32_t sVL = sVH + VT_B;

        // ---- scores ----
        float accs[16][4];
#pragma unroll
        for (int nt = 0; nt < 16; nt++)
#pragma unroll
            for (int r = 0; r < 4; r++) accs[nt][r] = 0.f;

#pragma unroll
        for (int ks = 0; ks < 4; ks++) {
            const uint32_t kOff = ks * 32;
            uint32_t ah[4], al[4];
            ldsm4(ah, sb + OFF_QH + qLane + kOff);
            ldsm4(al, sb + OFF_QL + qLane + kOff);
#pragma unroll
            for (int ntg = 0; ntg < 4; ntg++) {
                const uint32_t kAddr = ntg * (32 * 144) + kLane + kOff;
                uint32_t kh0[4], kh1[4], kl0[4], kl1[4];
                ldsm4(kh0, sKH + kAddr);
                ldsm4(kh1, sKH + kAddr + 16);
                ldsm4(kl0, sKL + kAddr);
                ldsm4(kl1, sKL + kAddr + 16);
#pragma unroll
                for (int q = 0; q < 4; q++) {
                    float* d = accs[ntg * 4 + q];
                    mma16816(d, ah[0], ah[1], ah[2], ah[3], kh0[q], kh1[q]);
                    mma16816(d, ah[0], ah[1], ah[2], ah[3], kl0[q], kl1[q]);
                    mma16816(d, al[0], al[1], al[2], al[3], kh0[q], kh1[q]);
                }
            }
        }

        // ---- online softmax ----
        float nm0 = m0, nm1 = m1;
#pragma unroll
        for (int nt = 0; nt < 16; nt++) {
            nm0 = fmaxf(nm0, fmaxf(accs[nt][0], accs[nt][1]));
            nm1 = fmaxf(nm1, fmaxf(accs[nt][2], accs[nt][3]));
        }
        nm0 = fmaxf(nm0, __shfl_xor_sync(0xffffffffu, nm0, 1));
        nm0 = fmaxf(nm0, __shfl_xor_sync(0xffffffffu, nm0, 2));
        nm1 = fmaxf(nm1, __shfl_xor_sync(0xffffffffu, nm1, 1));
        nm1 = fmaxf(nm1, __shfl_xor_sync(0xffffffffu, nm1, 2));
        const float corr0 = __expf(m0 - nm0);
        const float corr1 = __expf(m1 - nm1);
        float rs0 = 0.f, rs1 = 0.f;
#pragma unroll
        for (int nt = 0; nt < 16; nt++) {
            accs[nt][0] = __expf(accs[nt][0] - nm0);
            accs[nt][1] = __expf(accs[nt][1] - nm0);
            accs[nt][2] = __expf(accs[nt][2] - nm1);
            accs[nt][3] = __expf(accs[nt][3] - nm1);
            rs0 += accs[nt][0] + accs[nt][1];
            rs1 += accs[nt][2] + accs[nt][3];
        }
        rs0 += __shfl_xor_sync(0xffffffffu, rs0, 1);
        rs0 += __shfl_xor_sync(0xffffffffu, rs0, 2);
        rs1 += __shfl_xor_sync(0xffffffffu, rs1, 1);
        rs1 += __shfl_xor_sync(0xffffffffu, rs1, 2);
        l0 = l0 * corr0 + rs0;
        l1 = l1 * corr1 + rs1;
        m0 = nm0; m1 = nm1;
#pragma unroll
        for (int dt = 0; dt < 8; dt++) {
            acc_o[dt][0] *= corr0;
            acc_o[dt][1] *= corr0;
            acc_o[dt][2] *= corr1;
            acc_o[dt][3] *= corr1;
        }

        // ---- PV ----
#pragma unroll
        for (int kc = 0; kc < 8; kc++) {
            uint32_t pah[4], pal[4];
            pah[0] = splitp(accs[2 * kc][0],     accs[2 * kc][1],     pal[0]);
            pah[1] = splitp(accs[2 * kc][2],     accs[2 * kc][3],     pal[1]);
            pah[2] = splitp(accs[2 * kc + 1][0], accs[2 * kc + 1][1], pal[2]);
            pah[3] = splitp(accs[2 * kc + 1][2], accs[2 * kc + 1][3], pal[3]);
            const uint32_t vOff = kc * 32;
#pragma unroll
            for (int dtg = 0; dtg < 2; dtg++) {
                const uint32_t vAddr = dtg * (32 * 272) + vLane + vOff;
                uint32_t vh0[4], vh1[4], vl0[4], vl1[4];
                ldsm4(vh0, sVH + vAddr);
                ldsm4(vh1, sVH + vAddr + 16);
                ldsm4(vl0, sVL + vAddr);
                ldsm4(vl1, sVL + vAddr + 16);
#pragma unroll
                for (int q = 0; q < 4; q++) {
                    float* d = acc_o[dtg * 4 + q];
                    mma16816(d, pah[0], pah[1], pah[2], pah[3], vh0[q], vh1[q]);
                    mma16816(d, pah[0], pah[1], pah[2], pah[3], vl0[q], vl1[q]);
                    mma16816(d, pal[0], pal[1], pal[2], pal[3], vh0[q], vh1[q]);
                }
            }
        }
    }

    // ---- epilogue: write split bf16 output (A operand of o-proj) ----
    const float inv0 = 1.f / l0;
    const float inv1 = 1.f / l1;
    const size_t row0 = tok_base + q0 + wrow + g;
    const size_t row1 = row0 + 8;
#pragma unroll
    for (int dt = 0; dt < 8; dt++) {
        const int col = hcol + dt * 8 + tg * 2;
        uint32_t lo0, lo1;
        uint32_t hi0 = splitp(acc_o[dt][0] * inv0, acc_o[dt][1] * inv0, lo0);
        uint32_t hi1 = splitp(acc_o[dt][2] * inv1, acc_o[dt][3] * inv1, lo1);
        *(uint32_t*)&oh[row0 * QKV_ + col] = hi0;
        *(uint32_t*)&ol[row0 * QKV_ + col] = lo0;
        *(uint32_t*)&oh[row1 * QKV_ + col] = hi1;
        *(uint32_t*)&ol[row1 * QKV_ + col] = lo1;
    }
}

// ---------------------------------------------------------------------------
extern "C" void kernel_launch(void* const* d_in, const int* in_sizes, int n_in,
                              void* d_out, int out_size)
{
    const float* x     = (const float*)d_in[0];
    const float* w_qkv = (const float*)d_in[1];
    const float* b_qkv = (const float*)d_in[2];
    const float* w_o   = (const float*)d_in[3];
    const float* b_o   = (const float*)d_in[4];
    float* out = (float*)d_out;

    float *p_qkv;
    bf16 *p_xh, *p_xl, *p_wqh, *p_wql, *p_woh, *p_wol;
    bf16 *p_ath, *p_atl, *p_kh, *p_kl, *p_vh, *p_vl;
    cudaGetSymbolAddress((void**)&p_qkv, g_qkv);
    cudaGetSymbolAddress((void**)&p_xh, g_xh);
    cudaGetSymbolAddress((void**)&p_xl, g_xl);
    cudaGetSymbolAddress((void**)&p_wqh, g_wqh);
    cudaGetSymbolAddress((void**)&p_wql, g_wql);
    cudaGetSymbolAddress((void**)&p_woh, g_woh);
    cudaGetSymbolAddress((void**)&p_wol, g_wol);
    cudaGetSymbolAddress((void**)&p_ath, g_ath);
    cudaGetSymbolAddress((void**)&p_atl, g_atl);
    cudaGetSymbolAddress((void**)&p_kh, g_kh);
    cudaGetSymbolAddress((void**)&p_kl, g_kl);
    cudaGetSymbolAddress((void**)&p_vh, g_vh);
    cudaGetSymbolAddress((void**)&p_vl, g_vl);

    cudaFuncSetAttribute(gemm_bf, cudaFuncAttributeMaxDynamicSharedMemorySize,
                         GEMM_SMEM);
    cudaFuncSetAttribute(attn_tc, cudaFuncAttributeMaxDynamicSharedMemorySize,
                         ATT_SMEM);

    split_plain<<<(M_TOK * HID) / 2048, 256>>>(x, p_xh, p_xl);
    split_plain<<<(N_QKV * HID) / 2048, 256>>>(w_qkv, p_wqh, p_wql);
    split_plain<<<(HID * QKV_) / 2048, 256>>>(w_o, p_woh, p_wol);

    // 1) QKV projection (K columns emitted pre-split)
    {
        dim3 grid(N_QKV / 128, M_TOK / 128);
        gemm_bf<<<grid, 256, GEMM_SMEM>>>(p_xh, p_xl, p_wqh, p_wql, b_qkv, p_qkv,
                                          p_kh, p_kl, M_TOK, N_QKV, HID, 1);
    }
    // V transpose+split
    {
        dim3 grid(S_ / 64, B_ * H_);
        split_vt<<<grid, 256>>>(p_qkv, p_vh, p_vl);
    }
    // 2) attention (emits split output)
    {
        dim3 grid(S_ / 128, B_ * H_);
        attn_tc<<<grid, 256, ATT_SMEM>>>(p_qkv, p_kh, p_kl, p_vh, p_vl, p_ath, p_atl);
    }
    // 3) output projection
    {
        dim3 grid(QKV_ / 128, M_TOK / 128);
        gemm_bf<<<grid, 256, GEMM_SMEM>>>(p_ath, p_atl, p_woh, p_wol, b_o, out,
                                          nullptr, nullptr, M_TOK, QKV_, HID, 0);
    }
}

// round 9
// speedup vs baseline: 3.1754x; 1.3198x over previous
#include <cuda_runtime.h>
#include <cuda_bf16.h>
#include <math.h>
#include <stdint.h>

#define B_    2
#define S_    2048
#define H_    16
#define D_    64
#define HID   1024
#define QKV_  1024
#define M_TOK 4096
#define N_QKV 3072
#define SCALE 0.125f

typedef unsigned long long u64;
typedef __nv_bfloat16 bf16;

// ---------------- helpers ----------------------------------------------------
__device__ __forceinline__ uint32_t pkbf(bf16 x, bf16 y) {
    __nv_bfloat162 t; t.x = x; t.y = y;
    return *(uint32_t*)&t;
}
__device__ __forceinline__ uint32_t splitp(float x, float y, uint32_t& lo) {
    bf16 hx = __float2bfloat16(x), hy = __float2bfloat16(y);
    bf16 lx = __float2bfloat16(x - __bfloat162float(hx));
    bf16 ly = __float2bfloat16(y - __bfloat162float(hy));
    lo = pkbf(lx, ly);
    return pkbf(hx, hy);
}
__device__ __forceinline__ void mma16816(float* d,
    uint32_t a0, uint32_t a1, uint32_t a2, uint32_t a3, uint32_t b0, uint32_t b1) {
    asm volatile(
        "mma.sync.aligned.m16n8k16.row.col.f32.bf16.bf16.f32 "
        "{%0,%1,%2,%3},{%4,%5,%6,%7},{%8,%9},{%0,%1,%2,%3};"
        : "+f"(d[0]), "+f"(d[1]), "+f"(d[2]), "+f"(d[3])
        : "r"(a0), "r"(a1), "r"(a2), "r"(a3), "r"(b0), "r"(b1));
}
__device__ __forceinline__ void ldsm4(uint32_t* r, uint32_t addr) {
    asm volatile("ldmatrix.sync.aligned.m8n8.x4.shared.b16 {%0,%1,%2,%3},[%4];"
                 : "=r"(r[0]), "=r"(r[1]), "=r"(r[2]), "=r"(r[3]) : "r"(addr));
}
__device__ __forceinline__ uint32_t smem_u32(const void* p) {
    uint32_t a;
    asm("{ .reg .u64 t; cvta.to.shared.u64 t, %1; cvt.u32.u64 %0, t; }" : "=r"(a) : "l"(p));
    return a;
}
__device__ __forceinline__ void bulkcp(uint32_t dst, const void* src,
                                       uint32_t bytes, uint32_t mbar) {
    asm volatile(
        "cp.async.bulk.shared::cluster.global.mbarrier::complete_tx::bytes "
        "[%0], [%1], %2, [%3];"
        :: "r"(dst), "l"(src), "r"(bytes), "r"(mbar) : "memory");
}
#define MBAR_INIT(a, c) \
    asm volatile("mbarrier.init.shared.b64 [%0], %1;" :: "r"(a), "r"(c) : "memory")
#define MBAR_EXPECT(a, bytes) \
    asm volatile("mbarrier.arrive.expect_tx.shared.b64 _, [%0], %1;" \
                 :: "r"(a), "r"(bytes) : "memory")
#define MBAR_WAIT(a, ph) do {                                                  \
    uint32_t _m = (a); uint32_t _p = (ph); uint32_t _done;                     \
    asm volatile("{ .reg .pred p; mbarrier.try_wait.parity.acquire.cta.shared::cta.b64 p, [%1], %2;" \
                 " selp.b32 %0,1,0,p; }" : "=r"(_done) : "r"(_m), "r"(_p) : "memory"); \
    if (!_done) {                                                              \
        asm volatile("{ .reg .pred P1; WL_%=:"                                 \
                     " mbarrier.try_wait.parity.acquire.cta.shared::cta.b64 P1, [%0], %1, 0x989680;" \
                     " @P1 bra.uni WD_%=; bra.uni WL_%=; WD_%=: }"             \
                     :: "r"(_m), "r"(_p) : "memory");                          \
    }                                                                          \
} while (0)

// ---------------- tiled layout constants -------------------------------------
#define GLD2 40
#define APIECE (128 * GLD2)          // 5120 elems = 10240 B
#define AQLD 72
#define KPIECE (128 * AQLD)          // 9216 elems = 18432 B
#define AVLD 136
#define VPIECE (64 * AVLD)           // 8704 elems = 17408 B

// ---------------- scratch ----------------------------------------------------
__device__ float g_qkv[(size_t)M_TOK * N_QKV];
__device__ bf16 g_xh[(size_t)32 * 32 * APIECE],  g_xl[(size_t)32 * 32 * APIECE];
__device__ bf16 g_wqh[(size_t)24 * 32 * APIECE], g_wql[(size_t)24 * 32 * APIECE];
__device__ bf16 g_woh[(size_t)8 * 32 * APIECE],  g_wol[(size_t)8 * 32 * APIECE];
__device__ bf16 g_ath[(size_t)32 * 32 * APIECE], g_atl[(size_t)32 * 32 * APIECE];
__device__ bf16 g_kh[(size_t)512 * KPIECE],      g_kl[(size_t)512 * KPIECE];
__device__ bf16 g_vh[(size_t)512 * VPIECE],      g_vl[(size_t)512 * VPIECE];

// ---------------------------------------------------------------------------
// split pre-pass: fp32 row-major [R][C] -> tiled bf16 hi/lo pieces
// ---------------------------------------------------------------------------
__global__ __launch_bounds__(256) void split_tiled(
    const float* __restrict__ src, bf16* __restrict__ h, bf16* __restrict__ l, int C)
{
    const size_t e = ((size_t)blockIdx.x * 256 + threadIdx.x) * 8;
    const int r = (int)(e / C), c = (int)(e % C);
    float4 a = *(const float4*)(src + e);
    float4 b = *(const float4*)(src + e + 4);
    uint32_t l0, l1, l2, l3;
    uint32_t h0 = splitp(a.x, a.y, l0);
    uint32_t h1 = splitp(a.z, a.w, l1);
    uint32_t h2 = splitp(b.x, b.y, l2);
    uint32_t h3 = splitp(b.z, b.w, l3);
    const size_t dst = ((size_t)((r >> 7) * (C >> 5) + (c >> 5))) * APIECE
                     + (size_t)(r & 127) * GLD2 + (c & 31);
    *(uint4*)(h + dst) = make_uint4(h0, h1, h2, h3);
    *(uint4*)(l + dst) = make_uint4(l0, l1, l2, l3);
}

// V transpose+split into tiled [bh*16+kt] pieces of [64][AVLD]
__global__ __launch_bounds__(256) void split_vt(
    const float* __restrict__ qkv, bf16* __restrict__ vh, bf16* __restrict__ vl)
{
    __shared__ float T[64][65];
    const int st = blockIdx.x;     // 64-row s-tile, 0..31
    const int bh = blockIdx.y;
    const int b = bh >> 4, h = bh & 15;
    const int s0 = st * 64;
    const int tid = threadIdx.x;
    {
        const int sl = tid >> 2;
        const int cq = tid & 3;
        const float* src = qkv + ((size_t)(b * S_ + s0 + sl)) * N_QKV
                         + 2 * QKV_ + h * D_ + cq * 16;
#pragma unroll
        for (int j = 0; j < 4; j++) {
            float4 v = *(const float4*)(src + j * 4);
            T[cq * 16 + j * 4 + 0][sl] = v.x;
            T[cq * 16 + j * 4 + 1][sl] = v.y;
            T[cq * 16 + j * 4 + 2][sl] = v.z;
            T[cq * 16 + j * 4 + 3][sl] = v.w;
        }
    }
    __syncthreads();
    const int d = tid >> 2;
    const int sq = tid & 3;
    uint32_t hh[8], ll[8];
#pragma unroll
    for (int k = 0; k < 8; k++)
        hh[k] = splitp(T[d][sq * 16 + 2 * k], T[d][sq * 16 + 2 * k + 1], ll[k]);
    const size_t dst = (size_t)(bh * 16 + (st >> 1)) * VPIECE
                     + (size_t)d * AVLD + (st & 1) * 64 + sq * 16;
    *(uint4*)(vh + dst)     = make_uint4(hh[0], hh[1], hh[2], hh[3]);
    *(uint4*)(vh + dst + 8) = make_uint4(hh[4], hh[5], hh[6], hh[7]);
    *(uint4*)(vl + dst)     = make_uint4(ll[0], ll[1], ll[2], ll[3]);
    *(uint4*)(vl + dst + 8) = make_uint4(ll[4], ll[5], ll[6], ll[7]);
}

// ---------------------------------------------------------------------------
// Tensor-core NT GEMM: bulk-copy pipeline, 2 CTA/SM
// ---------------------------------------------------------------------------
#define GT_B (128 * GLD2 * 2)      // 10240
#define GST_B (4 * GT_B)           // 40960
#define GEMM_SMEM (2 * GST_B + 16) // + 2 mbarriers

__global__ __launch_bounds__(256, 2) void gemm_bf(
    const bf16* __restrict__ Ah, const bf16* __restrict__ Al,
    const bf16* __restrict__ Bh, const bf16* __restrict__ Bl,
    const float* __restrict__ bias, float* __restrict__ C,
    bf16* __restrict__ kh, bf16* __restrict__ kl,
    int M, int N, int K, int kmode)
{
    extern __shared__ char smem[];
    const uint32_t sb = smem_u32(smem);
    const uint32_t mbar = sb + 2 * GST_B;

    const int tid = threadIdx.x;
    const int wid = tid >> 5;
    const int lid = tid & 31;
    const int g   = lid >> 2;
    const int tg  = lid & 3;
    const int wm  = (wid & 1) * 64;
    const int wn  = (wid >> 1) * 32;
    const int bm  = blockIdx.y * 128;
    const int bn  = blockIdx.x * 128;

    const int kp = K >> 5;   // pieces along K
    const bf16* pAh = Ah + (size_t)blockIdx.y * kp * APIECE;
    const bf16* pAl = Al + (size_t)blockIdx.y * kp * APIECE;
    const bf16* pBh = Bh + (size_t)blockIdx.x * kp * APIECE;
    const bf16* pBl = Bl + (size_t)blockIdx.x * kp * APIECE;

    if (tid == 0) {
        MBAR_INIT(mbar, 1);
        MBAR_INIT(mbar + 8, 1);
    }
    __syncthreads();

    auto issue = [&](int buf, int c) {
        const uint32_t mb = mbar + buf * 8;
        const uint32_t d  = sb + buf * GST_B;
        MBAR_EXPECT(mb, GST_B);
        bulkcp(d,            pAh + (size_t)c * APIECE, GT_B, mb);
        bulkcp(d + GT_B,     pAl + (size_t)c * APIECE, GT_B, mb);
        bulkcp(d + 2 * GT_B, pBh + (size_t)c * APIECE, GT_B, mb);
        bulkcp(d + 3 * GT_B, pBl + (size_t)c * APIECE, GT_B, mb);
    };

    if (tid == 0) { issue(0, 0); issue(1, 1); }

    const uint32_t aLane = (uint32_t)((lid & 15) * GLD2 + ((lid >> 4) << 3)) * 2;
    const uint32_t bLane = (uint32_t)((wn + lid) * GLD2) * 2;

    float acc[4][4][4];
#pragma unroll
    for (int mi = 0; mi < 4; mi++)
#pragma unroll
        for (int ni = 0; ni < 4; ni++)
#pragma unroll
            for (int r = 0; r < 4; r++) acc[mi][ni][r] = 0.f;

    int ph0 = 0, ph1 = 0;
    for (int c = 0; c < kp; c++) {
        const int buf = c & 1;
        if (buf == 0) { MBAR_WAIT(mbar, ph0); ph0 ^= 1; }
        else          { MBAR_WAIT(mbar + 8, ph1); ph1 ^= 1; }

        const uint32_t sAH = sb + buf * GST_B;
        const uint32_t sAL = sAH + GT_B;
        const uint32_t sBH = sAH + 2 * GT_B;
        const uint32_t sBL = sAH + 3 * GT_B;

#pragma unroll
        for (int k2 = 0; k2 < 2; k2++) {
            const uint32_t kOff = k2 * 32;
            uint32_t bh0[4], bh1[4], bl0[4], bl1[4];
            ldsm4(bh0, sBH + bLane + kOff);
            ldsm4(bh1, sBH + bLane + kOff + 16);
            ldsm4(bl0, sBL + bLane + kOff);
            ldsm4(bl1, sBL + bLane + kOff + 16);
#pragma unroll
            for (int mi = 0; mi < 4; mi++) {
                const uint32_t rOff = (uint32_t)(wm + mi * 16) * 80 + aLane + kOff;
                uint32_t ah[4], al[4];
                ldsm4(ah, sAH + rOff);
                ldsm4(al, sAL + rOff);
#pragma unroll
                for (int ni = 0; ni < 4; ni++)
                    mma16816(acc[mi][ni], ah[0], ah[1], ah[2], ah[3], bh0[ni], bh1[ni]);
#pragma unroll
                for (int ni = 0; ni < 4; ni++)
                    mma16816(acc[mi][ni], ah[0], ah[1], ah[2], ah[3], bl0[ni], bl1[ni]);
#pragma unroll
                for (int ni = 0; ni < 4; ni++)
                    mma16816(acc[mi][ni], al[0], al[1], al[2], al[3], bh0[ni], bh1[ni]);
            }
        }
        __syncthreads();
        if (tid == 0 && c + 2 < kp) issue(buf, c + 2);
    }

    const bool ksplit = kmode && (bn >= QKV_) && (bn < 2 * QKV_);
    if (ksplit) {
#pragma unroll
        for (int ni = 0; ni < 4; ni++) {
            const int col = bn + wn + ni * 8 + tg * 2;
            const float bx = bias[col], by = bias[col + 1];
            const int colq = col - QKV_;
            const int hh = colq >> 6, dd = colq & 63;
#pragma unroll
            for (int mi = 0; mi < 4; mi++) {
                const int row = bm + wm + mi * 16 + g;
                uint32_t lo0, lo1;
                uint32_t hi0 = splitp(acc[mi][ni][0] + bx, acc[mi][ni][1] + by, lo0);
                uint32_t hi1 = splitp(acc[mi][ni][2] + bx, acc[mi][ni][3] + by, lo1);
#pragma unroll
                for (int rr = 0; rr < 2; rr++) {
                    const int r2 = row + rr * 8;
                    const size_t dst =
                        (size_t)((((r2 >> 11) << 4) + hh) * 16 + ((r2 >> 7) & 15)) * KPIECE
                        + (size_t)(r2 & 127) * AQLD + dd;
                    *(uint32_t*)&kh[dst] = rr ? hi1 : hi0;
                    *(uint32_t*)&kl[dst] = rr ? lo1 : lo0;
                }
            }
        }
    } else {
#pragma unroll
        for (int ni = 0; ni < 4; ni++) {
            const int col = bn + wn + ni * 8 + tg * 2;
            const float bx = bias[col], by = bias[col + 1];
#pragma unroll
            for (int mi = 0; mi < 4; mi++) {
                const int row = bm + wm + mi * 16 + g;
                float2 w0, w1;
                w0.x = acc[mi][ni][0] + bx;
                w0.y = acc[mi][ni][1] + by;
                w1.x = acc[mi][ni][2] + bx;
                w1.y = acc[mi][ni][3] + by;
                *(float2*)&C[(size_t)row * N + col]       = w0;
                *(float2*)&C[(size_t)(row + 8) * N + col] = w1;
            }
        }
    }
}

// ---------------------------------------------------------------------------
// Tensor-core flash attention with bulk-copy K/V pipeline
// ---------------------------------------------------------------------------
#define QT_B (128 * AQLD * 2)     // 18432
#define VT_B (64 * AVLD * 2)      // 17408
#define OFF_QH 0
#define OFF_QL QT_B
#define OFF_K0 (2 * QT_B)
#define OFF_V0 (2 * QT_B + 4 * QT_B)
#define ATT_SMEM (2 * QT_B + 4 * QT_B + 4 * VT_B + 16)

__global__ __launch_bounds__(256) void attn_tc(
    const float* __restrict__ qkv,
    const bf16* __restrict__ kh_g, const bf16* __restrict__ kl_g,
    const bf16* __restrict__ vh_g, const bf16* __restrict__ vl_g,
    bf16* __restrict__ oh, bf16* __restrict__ ol)
{
    extern __shared__ char smc[];
    const uint32_t sb = smem_u32(smc);
    const uint32_t mbar = sb + (ATT_SMEM - 16);
    bf16* Qh = (bf16*)(smc + OFF_QH);
    bf16* Ql = (bf16*)(smc + OFF_QL);

    const int tid = threadIdx.x;
    const int wid = tid >> 5;
    const int lid = tid & 31;
    const int g   = lid >> 2;
    const int tg  = lid & 3;
    const int qt  = blockIdx.x;
    const int bhx = blockIdx.y;
    const int b   = bhx >> 4;
    const int h   = bhx & 15;
    const int q0  = qt * 128;
    const size_t tok_base = (size_t)b * S_;
    const int hcol = h * D_;
    const int wrow = wid * 16;

    if (tid == 0) {
        MBAR_INIT(mbar, 1);
        MBAR_INIT(mbar + 8, 1);
    }

    // Q load: fp32 -> scaled hi/lo bf16
    {
        const int lr  = tid >> 1;
        const int lch = (tid & 1) * 32;
        const float* qp = qkv + (tok_base + q0 + lr) * (size_t)N_QKV + hcol + lch;
        const int base = lr * AQLD + lch;
#pragma unroll
        for (int j = 0; j < 8; j++) {
            float4 v = *(const float4*)(qp + j * 4);
            v.x *= SCALE; v.y *= SCALE; v.z *= SCALE; v.w *= SCALE;
            uint32_t lo0, lo1;
            uint32_t hi0 = splitp(v.x, v.y, lo0);
            uint32_t hi1 = splitp(v.z, v.w, lo1);
            *(uint32_t*)&Qh[base + j * 4]     = hi0;
            *(uint32_t*)&Qh[base + j * 4 + 2] = hi1;
            *(uint32_t*)&Ql[base + j * 4]     = lo0;
            *(uint32_t*)&Ql[base + j * 4 + 2] = lo1;
        }
    }
    __syncthreads();

    const bf16* pKh = kh_g + (size_t)bhx * 16 * KPIECE;
    const bf16* pKl = kl_g + (size_t)bhx * 16 * KPIECE;
    const bf16* pVh = vh_g + (size_t)bhx * 16 * VPIECE;
    const bf16* pVl = vl_g + (size_t)bhx * 16 * VPIECE;

    auto issue_kv = [&](int buf, int kt) {
        const uint32_t mb  = mbar + buf * 8;
        const uint32_t dkb = sb + OFF_K0 + buf * (2 * QT_B);
        const uint32_t dvb = sb + OFF_V0 + buf * (2 * VT_B);
        MBAR_EXPECT(mb, 2 * QT_B + 2 * VT_B);
        bulkcp(dkb,        pKh + (size_t)kt * KPIECE, QT_B, mb);
        bulkcp(dkb + QT_B, pKl + (size_t)kt * KPIECE, QT_B, mb);
        bulkcp(dvb,        pVh + (size_t)kt * VPIECE, VT_B, mb);
        bulkcp(dvb + VT_B, pVl + (size_t)kt * VPIECE, VT_B, mb);
    };

    if (tid == 0) { issue_kv(0, 0); issue_kv(1, 1); }

    const uint32_t qLane = (uint32_t)((wrow + (lid & 15)) * AQLD + ((lid >> 4) << 3)) * 2;
    const uint32_t kLane = (uint32_t)lid * 144;
    const uint32_t vLane = (uint32_t)lid * 272;

    float acc_o[8][4];
#pragma unroll
    for (int dt = 0; dt < 8; dt++)
#pragma unroll
        for (int r = 0; r < 4; r++) acc_o[dt][r] = 0.f;
    float m0 = -INFINITY, m1 = -INFINITY, l0 = 0.f, l1 = 0.f;

    int ph0 = 0, ph1 = 0;
    const int nkt = S_ / 128;
    for (int kt = 0; kt < nkt; kt++) {
        const int buf = kt & 1;
        if (buf == 0) { MBAR_WAIT(mbar, ph0); ph0 ^= 1; }
        else          { MBAR_WAIT(mbar + 8, ph1); ph1 ^= 1; }

        const uint32_t sKH = sb + OFF_K0 + buf * (2 * QT_B);
        const uint32_t sKL = sKH + QT_B;
        const uint32_t sVH = sb + OFF_V0 + buf * (2 * VT_B);
        const uint32_t sVL = sVH + VT_B;

        // ---- scores ----
        float accs[16][4];
#pragma unroll
        for (int nt = 0; nt < 16; nt++)
#pragma unroll
            for (int r = 0; r < 4; r++) accs[nt][r] = 0.f;

#pragma unroll
        for (int ks = 0; ks < 4; ks++) {
            const uint32_t kOff = ks * 32;
            uint32_t ah[4], al[4];
            ldsm4(ah, sb + OFF_QH + qLane + kOff);
            ldsm4(al, sb + OFF_QL + qLane + kOff);
#pragma unroll
            for (int ntg = 0; ntg < 4; ntg++) {
                const uint32_t kAddr = ntg * (32 * 144) + kLane + kOff;
                uint32_t kh0[4], kh1[4], kl0[4], kl1[4];
                ldsm4(kh0, sKH + kAddr);
                ldsm4(kh1, sKH + kAddr + 16);
                ldsm4(kl0, sKL + kAddr);
                ldsm4(kl1, sKL + kAddr + 16);
#pragma unroll
                for (int q = 0; q < 4; q++) {
                    float* d = accs[ntg * 4 + q];
                    mma16816(d, ah[0], ah[1], ah[2], ah[3], kh0[q], kh1[q]);
                    mma16816(d, ah[0], ah[1], ah[2], ah[3], kl0[q], kl1[q]);
                    mma16816(d, al[0], al[1], al[2], al[3], kh0[q], kh1[q]);
                }
            }
        }

        // ---- online softmax ----
        float nm0 = m0, nm1 = m1;
#pragma unroll
        for (int nt = 0; nt < 16; nt++) {
            nm0 = fmaxf(nm0, fmaxf(accs[nt][0], accs[nt][1]));
            nm1 = fmaxf(nm1, fmaxf(accs[nt][2], accs[nt][3]));
        }
        nm0 = fmaxf(nm0, __shfl_xor_sync(0xffffffffu, nm0, 1));
        nm0 = fmaxf(nm0, __shfl_xor_sync(0xffffffffu, nm0, 2));
        nm1 = fmaxf(nm1, __shfl_xor_sync(0xffffffffu, nm1, 1));
        nm1 = fmaxf(nm1, __shfl_xor_sync(0xffffffffu, nm1, 2));
        const float corr0 = __expf(m0 - nm0);
        const float corr1 = __expf(m1 - nm1);
        float rs0 = 0.f, rs1 = 0.f;
#pragma unroll
        for (int nt = 0; nt < 16; nt++) {
            accs[nt][0] = __expf(accs[nt][0] - nm0);
            accs[nt][1] = __expf(accs[nt][1] - nm0);
            accs[nt][2] = __expf(accs[nt][2] - nm1);
            accs[nt][3] = __expf(accs[nt][3] - nm1);
            rs0 += accs[nt][0] + accs[nt][1];
            rs1 += accs[nt][2] + accs[nt][3];
        }
        rs0 += __shfl_xor_sync(0xffffffffu, rs0, 1);
        rs0 += __shfl_xor_sync(0xffffffffu, rs0, 2);
        rs1 += __shfl_xor_sync(0xffffffffu, rs1, 1);
        rs1 += __shfl_xor_sync(0xffffffffu, rs1, 2);
        l0 = l0 * corr0 + rs0;
        l1 = l1 * corr1 + rs1;
        m0 = nm0; m1 = nm1;
#pragma unroll
        for (int dt = 0; dt < 8; dt++) {
            acc_o[dt][0] *= corr0;
            acc_o[dt][1] *= corr0;
            acc_o[dt][2] *= corr1;
            acc_o[dt][3] *= corr1;
        }

        // ---- PV ----
#pragma unroll
        for (int kc = 0; kc < 8; kc++) {
            uint32_t pah[4], pal[4];
            pah[0] = splitp(accs[2 * kc][0],     accs[2 * kc][1],     pal[0]);
            pah[1] = splitp(accs[2 * kc][2],     accs[2 * kc][3],     pal[1]);
            pah[2] = splitp(accs[2 * kc + 1][0], accs[2 * kc + 1][1], pal[2]);
            pah[3] = splitp(accs[2 * kc + 1][2], accs[2 * kc + 1][3], pal[3]);
            const uint32_t vOff = kc * 32;
#pragma unroll
            for (int dtg = 0; dtg < 2; dtg++) {
                const uint32_t vAddr = dtg * (32 * 272) + vLane + vOff;
                uint32_t vh0[4], vh1[4], vl0[4], vl1[4];
                ldsm4(vh0, sVH + vAddr);
                ldsm4(vh1, sVH + vAddr + 16);
                ldsm4(vl0, sVL + vAddr);
                ldsm4(vl1, sVL + vAddr + 16);
#pragma unroll
                for (int q = 0; q < 4; q++) {
                    float* d = acc_o[dtg * 4 + q];
                    mma16816(d, pah[0], pah[1], pah[2], pah[3], vh0[q], vh1[q]);
                    mma16816(d, pah[0], pah[1], pah[2], pah[3], vl0[q], vl1[q]);
                    mma16816(d, pal[0], pal[1], pal[2], pal[3], vh0[q], vh1[q]);
                }
            }
        }
        __syncthreads();
        if (tid == 0 && kt + 2 < nkt) issue_kv(buf, kt + 2);
    }

    // ---- epilogue: write tiled split bf16 output (A operand of o-proj) ----
    const float inv0 = 1.f / l0;
    const float inv1 = 1.f / l1;
    const int row0 = (int)(tok_base + q0 + wrow + g);
#pragma unroll
    for (int dt = 0; dt < 8; dt++) {
        const int col = hcol + dt * 8 + tg * 2;
        uint32_t lo0, lo1;
        uint32_t hi0 = splitp(acc_o[dt][0] * inv0, acc_o[dt][1] * inv0, lo0);
        uint32_t hi1 = splitp(acc_o[dt][2] * inv1, acc_o[dt][3] * inv1, lo1);
#pragma unroll
        for (int rr = 0; rr < 2; rr++) {
            const int r2 = row0 + rr * 8;
            const size_t dst = ((size_t)((r2 >> 7) * 32 + (col >> 5))) * APIECE
                             + (size_t)(r2 & 127) * GLD2 + (col & 31);
            *(uint32_t*)&oh[dst] = rr ? hi1 : hi0;
            *(uint32_t*)&ol[dst] = rr ? lo1 : lo0;
        }
    }
}

// ---------------------------------------------------------------------------
extern "C" void kernel_launch(void* const* d_in, const int* in_sizes, int n_in,
                              void* d_out, int out_size)
{
    const float* x     = (const float*)d_in[0];
    const float* w_qkv = (const float*)d_in[1];
    const float* b_qkv = (const float*)d_in[2];
    const float* w_o   = (const float*)d_in[3];
    const float* b_o   = (const float*)d_in[4];
    float* out = (float*)d_out;

    float *p_qkv;
    bf16 *p_xh, *p_xl, *p_wqh, *p_wql, *p_woh, *p_wol;
    bf16 *p_ath, *p_atl, *p_kh, *p_kl, *p_vh, *p_vl;
    cudaGetSymbolAddress((void**)&p_qkv, g_qkv);
    cudaGetSymbolAddress((void**)&p_xh, g_xh);
    cudaGetSymbolAddress((void**)&p_xl, g_xl);
    cudaGetSymbolAddress((void**)&p_wqh, g_wqh);
    cudaGetSymbolAddress((void**)&p_wql, g_wql);
    cudaGetSymbolAddress((void**)&p_woh, g_woh);
    cudaGetSymbolAddress((void**)&p_wol, g_wol);
    cudaGetSymbolAddress((void**)&p_ath, g_ath);
    cudaGetSymbolAddress((void**)&p_atl, g_atl);
    cudaGetSymbolAddress((void**)&p_kh, g_kh);
    cudaGetSymbolAddress((void**)&p_kl, g_kl);
    cudaGetSymbolAddress((void**)&p_vh, g_vh);
    cudaGetSymbolAddress((void**)&p_vl, g_vl);

    cudaFuncSetAttribute(gemm_bf, cudaFuncAttributeMaxDynamicSharedMemorySize,
                         GEMM_SMEM);
    cudaFuncSetAttribute(attn_tc, cudaFuncAttributeMaxDynamicSharedMemorySize,
                         ATT_SMEM);

    split_tiled<<<(M_TOK * HID) / 2048, 256>>>(x, p_xh, p_xl, HID);
    split_tiled<<<(N_QKV * HID) / 2048, 256>>>(w_qkv, p_wqh, p_wql, HID);
    split_tiled<<<(HID * QKV_) / 2048, 256>>>(w_o, p_woh, p_wol, QKV_);

    // 1) QKV projection (K columns emitted pre-split tiled)
    {
        dim3 grid(N_QKV / 128, M_TOK / 128);
        gemm_bf<<<grid, 256, GEMM_SMEM>>>(p_xh, p_xl, p_wqh, p_wql, b_qkv, p_qkv,
                                          p_kh, p_kl, M_TOK, N_QKV, HID, 1);
    }
    // V transpose+split (tiled)
    {
        dim3 grid(S_ / 64, B_ * H_);
        split_vt<<<grid, 256>>>(p_qkv, p_vh, p_vl);
    }
    // 2) attention (emits tiled split output)
    {
        dim3 grid(S_ / 128, B_ * H_);
        attn_tc<<<grid, 256, ATT_SMEM>>>(p_qkv, p_kh, p_kl, p_vh, p_vl, p_ath, p_atl);
    }
    // 3) output projection
    {
        dim3 grid(QKV_ / 128, M_TOK / 128);
        gemm_bf<<<grid, 256, GEMM_SMEM>>>(p_ath, p_atl, p_woh, p_wol, b_o, out,
                                          nullptr, nullptr, M_TOK, QKV_, HID, 0);
    }
}